// round 8
// baseline (speedup 1.0000x reference)
#include <cuda_runtime.h>
#include <cuda_bf16.h>
#include <stdint.h>
#include <math.h>

#define BD 8
#define TT 1024
#define NE 1024
#define NH 16
#define HS 64
#define BT (BD * TT)     // 8192
#define FF (4 * NE)      // 4096

// ---------------- scratch (alloc-guard-safe device globals) ----------------
__device__ float g_xn1[BT * NE];
__device__ __nv_bfloat16 g_xn1h[BT * NE], g_xn1l[BT * NE];
__device__ float g_q[NH * BT * HS], g_k[NH * BT * HS], g_v[NH * BT * HS];
__device__ __nv_bfloat16 g_atth[BT * NE], g_attl[BT * NE];
__device__ float g_y1[BT * NE];
__device__ float g_xn2[BT * NE];
__device__ __nv_bfloat16 g_xn2h[BT * NE], g_xn2l[BT * NE];
__device__ __nv_bfloat16 g_hh[(long)BT * FF], g_hl[(long)BT * FF];
// transposed (N-major, K-contig) split weights
__device__ __nv_bfloat16 g_wqkvh[3 * NE * NE], g_wqkvl[3 * NE * NE];  // [3072][1024]
__device__ __nv_bfloat16 g_wph[NE * NE],  g_wpl[NE * NE];             // [1024][1024]
__device__ __nv_bfloat16 g_w1h[FF * NE],  g_w1l[FF * NE];             // [4096][1024]
__device__ __nv_bfloat16 g_w2h[NE * FF],  g_w2l[NE * FF];             // [1024][4096]

// ---------------- helpers ----------------
__device__ __forceinline__ uint32_t smem_u32(const void* p) {
    uint32_t a;
    asm("{ .reg .u64 t; cvta.to.shared.u64 t, %1; cvt.u32.u64 %0, t; }"
        : "=r"(a) : "l"(p));
    return a;
}
__device__ __forceinline__ void splitf(float v, __nv_bfloat16& h, __nv_bfloat16& l) {
    h = __float2bfloat16(v);
    l = __float2bfloat16(v - __bfloat162float(h));
}
__device__ __forceinline__ void cp16(uint32_t dst, const void* src) {
    asm volatile("cp.async.ca.shared.global [%0], [%1], 16;"
                 :: "r"(dst), "l"(src) : "memory");
}
__device__ __forceinline__ void cp_commit() {
    asm volatile("cp.async.commit_group;" ::: "memory");
}
template <int N>
__device__ __forceinline__ void cp_wait() {
    asm volatile("cp.async.wait_group %0;" :: "n"(N) : "memory");
}
// NOTE: not volatile — constraints are complete, lets ptxas schedule freely.
__device__ __forceinline__ void mma16816(float* c, const uint32_t* a,
                                         const uint32_t* b) {
    asm("mma.sync.aligned.m16n8k16.row.col.f32.bf16.bf16.f32 "
        "{%0,%1,%2,%3}, {%4,%5,%6,%7}, {%8,%9}, {%0,%1,%2,%3};"
        : "+f"(c[0]), "+f"(c[1]), "+f"(c[2]), "+f"(c[3])
        : "r"(a[0]), "r"(a[1]), "r"(a[2]), "r"(a[3]), "r"(b[0]), "r"(b[1]));
}
__device__ __forceinline__ void ldsm4(uint32_t* r, uint32_t addr) {
    asm volatile("ldmatrix.sync.aligned.m8n8.x4.shared.b16 {%0,%1,%2,%3}, [%4];"
                 : "=r"(r[0]), "=r"(r[1]), "=r"(r[2]), "=r"(r[3]) : "r"(addr));
}

// ---------------- layernorm: fp32 out + bf16 hi/lo out ----------------
__global__ __launch_bounds__(256) void ln_kernel(const float* __restrict__ x,
                                                 const float* __restrict__ g,
                                                 const float* __restrict__ be,
                                                 float* __restrict__ y,
                                                 __nv_bfloat16* __restrict__ yh,
                                                 __nv_bfloat16* __restrict__ yl) {
    __shared__ float sred[16];
    long row = blockIdx.x;
    const float4* xr = (const float4*)(x + row * NE);
    int tid = threadIdx.x;
    float4 t = xr[tid];
    float s  = t.x + t.y + t.z + t.w;
    float s2 = t.x * t.x + t.y * t.y + t.z * t.z + t.w * t.w;
    #pragma unroll
    for (int o = 16; o; o >>= 1) {
        s  += __shfl_xor_sync(0xffffffffu, s,  o);
        s2 += __shfl_xor_sync(0xffffffffu, s2, o);
    }
    int w = tid >> 5;
    if ((tid & 31) == 0) { sred[w] = s; sred[8 + w] = s2; }
    __syncthreads();
    if (tid < 32) {
        float a  = (tid < 8) ? sred[tid]     : 0.f;
        float a2 = (tid < 8) ? sred[8 + tid] : 0.f;
        #pragma unroll
        for (int o = 4; o; o >>= 1) {
            a  += __shfl_xor_sync(0xffffffffu, a,  o);
            a2 += __shfl_xor_sync(0xffffffffu, a2, o);
        }
        if (tid == 0) { sred[0] = a; sred[1] = a2; }
    }
    __syncthreads();
    float mean = sred[0] * (1.f / NE);
    float var  = sred[1] * (1.f / NE) - mean * mean;
    float rstd = rsqrtf(var + 1e-5f);
    float4 gg = ((const float4*)g)[tid];
    float4 bb = ((const float4*)be)[tid];
    float4 o;
    o.x = (t.x - mean) * rstd * gg.x + bb.x;
    o.y = (t.y - mean) * rstd * gg.y + bb.y;
    o.z = (t.z - mean) * rstd * gg.z + bb.z;
    o.w = (t.w - mean) * rstd * gg.w + bb.w;
    ((float4*)(y + row * NE))[tid] = o;
    __nv_bfloat16 h0, l0, h1, l1, h2, l2, h3, l3;
    splitf(o.x, h0, l0); splitf(o.y, h1, l1);
    splitf(o.z, h2, l2); splitf(o.w, h3, l3);
    __nv_bfloat162 H0; H0.x = h0; H0.y = h1;
    __nv_bfloat162 H1; H1.x = h2; H1.y = h3;
    __nv_bfloat162 L0; L0.x = l0; L0.y = l1;
    __nv_bfloat162 L1; L1.x = l2; L1.y = l3;
    __nv_bfloat162* ph = (__nv_bfloat162*)(yh + row * NE);
    __nv_bfloat162* pl = (__nv_bfloat162*)(yl + row * NE);
    ph[tid * 2] = H0; ph[tid * 2 + 1] = H1;
    pl[tid * 2] = L0; pl[tid * 2 + 1] = L1;
}

// ---------------- weight prep: transpose + bf16 split ----------------
__global__ __launch_bounds__(256) void tconv_kernel(const float* __restrict__ src,
                                                    __nv_bfloat16* __restrict__ dh,
                                                    __nv_bfloat16* __restrict__ dl,
                                                    int R, int C, int RS, int RO) {
    __shared__ float tile[32][33];
    int tx = threadIdx.x, ty = threadIdx.y;
    int x0 = blockIdx.x * 32, y0 = blockIdx.y * 32;
    #pragma unroll
    for (int i = 0; i < 4; i++)
        tile[ty + 8 * i][tx] = src[(long)(y0 + ty + 8 * i) * C + x0 + tx];
    __syncthreads();
    #pragma unroll
    for (int i = 0; i < 4; i++) {
        int c = x0 + ty + 8 * i;
        float v = tile[tx][ty + 8 * i];
        __nv_bfloat16 h, l; splitf(v, h, l);
        long di = (long)(RO + c) * RS + y0 + tx;
        dh[di] = h; dl[di] = l;
    }
}
__global__ __launch_bounds__(256) void qkv_prep_kernel(const float* __restrict__ wq,
                                                       const float* __restrict__ wk,
                                                       const float* __restrict__ wv,
                                                       __nv_bfloat16* __restrict__ dh,
                                                       __nv_bfloat16* __restrict__ dl) {
    __shared__ float tile[32][33];
    int z = blockIdx.z, which = z >> 4, h = z & 15;
    const float* src = ((which == 0) ? wq : (which == 1) ? wk : wv) + (long)h * NE * HS;
    int RO = which * NE + h * HS;
    int tx = threadIdx.x, ty = threadIdx.y;
    int x0 = blockIdx.x * 32, y0 = blockIdx.y * 32;
    #pragma unroll
    for (int i = 0; i < 4; i++)
        tile[ty + 8 * i][tx] = src[(long)(y0 + ty + 8 * i) * HS + x0 + tx];
    __syncthreads();
    #pragma unroll
    for (int i = 0; i < 4; i++) {
        int c = x0 + ty + 8 * i;
        float v = tile[tx][ty + 8 * i];
        __nv_bfloat16 hh, ll; splitf(v, hh, ll);
        long di = (long)(RO + c) * NE + y0 + tx;
        dh[di] = hh; dl[di] = ll;
    }
}

// ---------------- warp-MMA split-bf16 GEMM (ldmatrix + 3-stage cp.async) ----
// C[M, Ndim] = (Ah+Al)[M,K] @ (Bh+Bl)[Ndim,K]^T, 3-term split, fp32 accum.
// CTA tile 128x128, 8 warps (4m x 2n), warp tile 32x64, K-chunk 32, 3 stages.
// MMA issue order is term-outermost: 16 independent accumulators between
// reuses of any accumulator -> HMMA latency fully pipelined.
#define KC 32
#define ROWB 80                       // bytes per smem row (32 bf16 + pad)
#define MATB (128 * ROWB)             // 10240 B per matrix tile
#define STAGEB (4 * MATB)             // 40960 B per stage
#define SMTOT (3 * STAGEB)            // 122880 B

__global__ __launch_bounds__(256, 1) void mma_gemm(
    const __nv_bfloat16* __restrict__ Ah, const __nv_bfloat16* __restrict__ Al,
    const __nv_bfloat16* __restrict__ Bh, const __nv_bfloat16* __restrict__ Bl,
    int Kdim, int Ndim,
    const float* __restrict__ bias, const float* __restrict__ res,
    float* __restrict__ Cf,
    __nv_bfloat16* __restrict__ Ch, __nv_bfloat16* __restrict__ Cl,
    float* __restrict__ Qo, float* __restrict__ Ko, float* __restrict__ Vo,
    int mode) {
    extern __shared__ char smem[];
    uint32_t sb = smem_u32(smem);
    int tid = threadIdx.x;
    int wid = tid >> 5, lane = tid & 31;
    int warp_m = wid & 3, warp_n = wid >> 2;   // 4 x 2
    int r4 = lane >> 2, qp = lane & 3;
    int m0 = blockIdx.y * 128, n0 = blockIdx.x * 128;

    // per-lane ldmatrix base offsets (within a stage)
    uint32_t a_off = (uint32_t)(warp_m * 32 + (lane & 15)) * ROWB + ((lane >> 4) << 4);
    uint32_t b_off = (uint32_t)(warp_n * 64 + ((lane >> 4) << 3) + (lane & 7)) * ROWB
                     + (((lane >> 3) & 1) << 4);

    float acc[2][8][4];
    #pragma unroll
    for (int mt = 0; mt < 2; mt++)
        #pragma unroll
        for (int nt = 0; nt < 8; nt++)
            #pragma unroll
            for (int e = 0; e < 4; e++) acc[mt][nt][e] = 0.f;

    int nch = Kdim / KC;

    auto issue = [&](int c, int st) {
        int k0 = c * KC;
        uint32_t sbase = sb + st * STAGEB;
        #pragma unroll
        for (int j = 0; j < 8; j++) {
            int i = tid + j * 256;            // 0..2047
            int mat = i >> 9;                 // 0..3
            int rem = i & 511;
            int r = rem >> 2, cc = rem & 3;   // row, 16B-chunk
            const __nv_bfloat16* base =
                (mat == 0) ? Ah : (mat == 1) ? Al : (mat == 2) ? Bh : Bl;
            long grow = (mat < 2) ? ((long)(m0 + r) * Kdim)
                                  : ((long)(n0 + r) * Kdim);
            cp16(sbase + mat * MATB + r * ROWB + cc * 16,
                 base + grow + k0 + cc * 8);
        }
        cp_commit();
    };

    issue(0, 0);
    issue(1, 1);
    for (int c = 0; c < nch; c++) {
        int st = c % 3;
        if (c + 2 < nch) issue(c + 2, (c + 2) % 3);
        cp_wait<2>();
        __syncthreads();

        uint32_t stage = sb + st * STAGEB;
        #pragma unroll
        for (int ks = 0; ks < 2; ks++) {
            uint32_t ko = ks * 32;            // 16 bf16 = 32B per k-step
            uint32_t ah[2][4], al[2][4], bh[4][4], bl[4][4];
            #pragma unroll
            for (int mt = 0; mt < 2; mt++) {
                uint32_t ra = stage + a_off + mt * (16 * ROWB) + ko;
                ldsm4(ah[mt], ra);
                ldsm4(al[mt], ra + MATB);
            }
            #pragma unroll
            for (int np = 0; np < 4; np++) {
                uint32_t rb = stage + 2 * MATB + b_off + np * (16 * ROWB) + ko;
                ldsm4(bh[np], rb);
                ldsm4(bl[np], rb + MATB);
            }
            // term 1: ah*bh (16 independent MMAs)
            #pragma unroll
            for (int mt = 0; mt < 2; mt++)
                #pragma unroll
                for (int np = 0; np < 4; np++) {
                    mma16816(acc[mt][np * 2],     ah[mt], &bh[np][0]);
                    mma16816(acc[mt][np * 2 + 1], ah[mt], &bh[np][2]);
                }
            // term 2: ah*bl
            #pragma unroll
            for (int mt = 0; mt < 2; mt++)
                #pragma unroll
                for (int np = 0; np < 4; np++) {
                    mma16816(acc[mt][np * 2],     ah[mt], &bl[np][0]);
                    mma16816(acc[mt][np * 2 + 1], ah[mt], &bl[np][2]);
                }
            // term 3: al*bh
            #pragma unroll
            for (int mt = 0; mt < 2; mt++)
                #pragma unroll
                for (int np = 0; np < 4; np++) {
                    mma16816(acc[mt][np * 2],     al[mt], &bh[np][0]);
                    mma16816(acc[mt][np * 2 + 1], al[mt], &bh[np][2]);
                }
        }
        __syncthreads();
    }

    // epilogue: c0,c1 at (r, n..n+1); c2,c3 at (r+8, n..n+1)
    #pragma unroll
    for (int mt = 0; mt < 2; mt++) {
        int gm0 = m0 + warp_m * 32 + mt * 16 + r4;
        #pragma unroll
        for (int nt = 0; nt < 8; nt++) {
            int gn = n0 + warp_n * 64 + nt * 8 + 2 * qp;
            #pragma unroll
            for (int half = 0; half < 2; half++) {
                long gm = gm0 + half * 8;
                float v0 = acc[mt][nt][half * 2];
                float v1 = acc[mt][nt][half * 2 + 1];
                if (mode == 1) {
                    int which = gn >> 10, hd = (gn >> 6) & 15, e = gn & 63;
                    float* basew = (which == 0) ? Qo : (which == 1) ? Ko : Vo;
                    float2 t; t.x = v0; t.y = v1;
                    *(float2*)(basew + ((long)hd * BT + gm) * HS + e) = t;
                } else if (mode == 2) {
                    v0 = fmaxf(v0 + bias[gn], 0.f);
                    v1 = fmaxf(v1 + bias[gn + 1], 0.f);
                    __nv_bfloat16 h0, l0, h1, l1;
                    splitf(v0, h0, l0); splitf(v1, h1, l1);
                    __nv_bfloat162 H; H.x = h0; H.y = h1;
                    __nv_bfloat162 L; L.x = l0; L.y = l1;
                    long idx = (gm * (long)Ndim + gn) >> 1;
                    ((__nv_bfloat162*)Ch)[idx] = H;
                    ((__nv_bfloat162*)Cl)[idx] = L;
                } else {
                    if (bias) { v0 += bias[gn]; v1 += bias[gn + 1]; }
                    if (res) {
                        float2 rr = *(const float2*)(res + gm * (long)Ndim + gn);
                        v0 += rr.x; v1 += rr.y;
                    }
                    float2 t; t.x = v0; t.y = v1;
                    *(float2*)(Cf + gm * (long)Ndim + gn) = t;
                }
            }
        }
    }
}

// ---------------- causal attention (fp32), bf16 hi/lo output ----------------
__global__ __launch_bounds__(128) void attn_kernel(const float* __restrict__ Q,
                                                   const float* __restrict__ K,
                                                   const float* __restrict__ V,
                                                   __nv_bfloat16* __restrict__ Oh,
                                                   __nv_bfloat16* __restrict__ Ol) {
    __shared__ float Ks[64][64];
    __shared__ float Vs[64][64];
    int q0 = blockIdx.x * 64;
    int h  = blockIdx.y;
    int b  = blockIdx.z;
    long base = ((long)h * BT + (long)b * TT) * HS;
    const float* Qp = Q + base;
    const float* Kp = K + base;
    const float* Vp = V + base;

    int tid = threadIdx.x, qi = tid >> 1, half = tid & 1;
    int tq = q0 + qi;

    float qreg[32], acc[32];
    #pragma unroll
    for (int e = 0; e < 32; e++) acc[e] = 0.f;
    {
        const float4* qrow = (const float4*)(Qp + (long)tq * HS + half * 32);
        #pragma unroll
        for (int e4 = 0; e4 < 8; e4++) {
            float4 t = qrow[e4];
            qreg[e4 * 4 + 0] = t.x; qreg[e4 * 4 + 1] = t.y;
            qreg[e4 * 4 + 2] = t.z; qreg[e4 * 4 + 3] = t.w;
        }
    }
    const float scale = 0.125f;
    float lsum = 0.f;

    for (int s0 = 0; s0 <= q0; s0 += 64) {
        __syncthreads();
        for (int i = tid; i < 64 * 16; i += 128) {
            int r = i >> 4, c4 = (i & 15) << 2;
            *(float4*)&Ks[r][c4] = *(const float4*)(Kp + (long)(s0 + r) * HS + c4);
            *(float4*)&Vs[r][c4] = *(const float4*)(Vp + (long)(s0 + r) * HS + c4);
        }
        __syncthreads();
        bool diag = (s0 == q0);
        #pragma unroll 4
        for (int j = 0; j < 64; j++) {
            float s = 0.f;
            const float* kr = &Ks[j][half * 32];
            #pragma unroll
            for (int e = 0; e < 32; e++) s = fmaf(qreg[e], kr[e], s);
            s += __shfl_xor_sync(0xffffffffu, s, 1);
            s *= scale;
            float pe = (!diag || (s0 + j <= tq)) ? __expf(s) : 0.f;
            lsum += pe;
            const float* vr = &Vs[j][half * 32];
            #pragma unroll
            for (int e = 0; e < 32; e++) acc[e] = fmaf(pe, vr[e], acc[e]);
        }
    }
    float inv = 1.f / lsum;
    long ocol = (long)(b * TT + tq) * NE + h * HS + half * 32;
    __nv_bfloat162* ph = (__nv_bfloat162*)(Oh + ocol);
    __nv_bfloat162* pl = (__nv_bfloat162*)(Ol + ocol);
    #pragma unroll
    for (int e2 = 0; e2 < 16; e2++) {
        float v0 = acc[e2 * 2] * inv, v1 = acc[e2 * 2 + 1] * inv;
        __nv_bfloat16 h0, l0, h1, l1;
        splitf(v0, h0, l0); splitf(v1, h1, l1);
        __nv_bfloat162 H; H.x = h0; H.y = h1;
        __nv_bfloat162 L; L.x = l0; L.y = l1;
        ph[e2] = H; pl[e2] = L;
    }
}

// ---------------- launch ----------------
extern "C" void kernel_launch(void* const* d_in, const int* in_sizes, int n_in,
                              void* d_out, int out_size) {
    const float* x      = (const float*)d_in[0];
    const float* wq     = (const float*)d_in[1];
    const float* wk     = (const float*)d_in[2];
    const float* wv     = (const float*)d_in[3];
    const float* w_proj = (const float*)d_in[4];
    const float* b_proj = (const float*)d_in[5];
    const float* w1     = (const float*)d_in[6];
    const float* b1     = (const float*)d_in[7];
    const float* w2     = (const float*)d_in[8];
    const float* b2     = (const float*)d_in[9];
    const float* g1     = (const float*)d_in[10];
    const float* be1    = (const float*)d_in[11];
    const float* g2     = (const float*)d_in[12];
    const float* be2    = (const float*)d_in[13];
    float* out = (float*)d_out;

    float *xn1, *q, *k, *v, *y1, *xn2;
    __nv_bfloat16 *xn1h, *xn1l, *atth, *attl, *xn2h, *xn2l, *hh, *hl;
    __nv_bfloat16 *wqkvh, *wqkvl, *wph, *wpl, *w1h, *w1l, *w2h, *w2l;
    cudaGetSymbolAddress((void**)&xn1,  g_xn1);
    cudaGetSymbolAddress((void**)&xn1h, g_xn1h);
    cudaGetSymbolAddress((void**)&xn1l, g_xn1l);
    cudaGetSymbolAddress((void**)&q,    g_q);
    cudaGetSymbolAddress((void**)&k,    g_k);
    cudaGetSymbolAddress((void**)&v,    g_v);
    cudaGetSymbolAddress((void**)&atth, g_atth);
    cudaGetSymbolAddress((void**)&attl, g_attl);
    cudaGetSymbolAddress((void**)&y1,   g_y1);
    cudaGetSymbolAddress((void**)&xn2,  g_xn2);
    cudaGetSymbolAddress((void**)&xn2h, g_xn2h);
    cudaGetSymbolAddress((void**)&xn2l, g_xn2l);
    cudaGetSymbolAddress((void**)&hh,   g_hh);
    cudaGetSymbolAddress((void**)&hl,   g_hl);
    cudaGetSymbolAddress((void**)&wqkvh, g_wqkvh);
    cudaGetSymbolAddress((void**)&wqkvl, g_wqkvl);
    cudaGetSymbolAddress((void**)&wph,  g_wph);
    cudaGetSymbolAddress((void**)&wpl,  g_wpl);
    cudaGetSymbolAddress((void**)&w1h,  g_w1h);
    cudaGetSymbolAddress((void**)&w1l,  g_w1l);
    cudaGetSymbolAddress((void**)&w2h,  g_w2h);
    cudaGetSymbolAddress((void**)&w2l,  g_w2l);

    cudaFuncSetAttribute(mma_gemm, cudaFuncAttributeMaxDynamicSharedMemorySize, SMTOT);

    dim3 tb32(32, 8);
    // weight prep (transpose + split)
    qkv_prep_kernel<<<dim3(2, 32, 48), tb32>>>(wq, wk, wv, wqkvh, wqkvl);
    tconv_kernel<<<dim3(32, 32), tb32>>>(w_proj, wph, wpl, NE, NE, NE, 0);
    tconv_kernel<<<dim3(128, 32), tb32>>>(w1, w1h, w1l, NE, FF, NE, 0);
    tconv_kernel<<<dim3(32, 128), tb32>>>(w2, w2h, w2l, FF, NE, FF, 0);

    // 1) layernorm1
    ln_kernel<<<BT, 256>>>(x, g1, be1, xn1, xn1h, xn1l);

    // 2) fused QKV: [8192,1024] @ WTqkv[3072,1024]^T, scatter to q/k/v
    mma_gemm<<<dim3(24, 64), 256, SMTOT>>>(xn1h, xn1l, wqkvh, wqkvl, NE, 3 * NE,
                                           nullptr, nullptr, nullptr, nullptr, nullptr,
                                           q, k, v, 1);
    // 3) attention (fp32 in, bf16 hi/lo out)
    attn_kernel<<<dim3(TT / 64, NH, BD), 128>>>(q, k, v, atth, attl);

    // 4) proj + bias + residual(xn1) -> y1
    mma_gemm<<<dim3(8, 64), 256, SMTOT>>>(atth, attl, wph, wpl, NE, NE,
                                          b_proj, xn1, y1, nullptr, nullptr,
                                          nullptr, nullptr, nullptr, 0);
    // 5) layernorm2
    ln_kernel<<<BT, 256>>>(y1, g2, be2, xn2, xn2h, xn2l);

    // 6) FFN1 + bias + relu -> h (bf16 hi/lo)
    mma_gemm<<<dim3(32, 64), 256, SMTOT>>>(xn2h, xn2l, w1h, w1l, NE, FF,
                                           b1, nullptr, nullptr, hh, hl,
                                           nullptr, nullptr, nullptr, 2);
    // 7) FFN2 + bias + residual(xn2) -> out
    mma_gemm<<<dim3(8, 64), 256, SMTOT>>>(hh, hl, w2h, w2l, FF, NE,
                                          b2, xn2, out, nullptr, nullptr,
                                          nullptr, nullptr, nullptr, 0);
}

// round 11
// speedup vs baseline: 1.6993x; 1.6993x over previous
#include <cuda_runtime.h>
#include <cuda_bf16.h>
#include <stdint.h>
#include <math.h>

#define BD 8
#define TT 1024
#define NE 1024
#define NH 16
#define HS 64
#define BT (BD * TT)     // 8192
#define FF (4 * NE)      // 4096

// ---------------- scratch (alloc-guard-safe device globals) ----------------
__device__ float g_xn1[BT * NE];
__device__ __nv_bfloat16 g_xn1h[BT * NE], g_xn1l[BT * NE];
__device__ float g_q[NH * BT * HS], g_k[NH * BT * HS], g_v[NH * BT * HS];
__device__ __nv_bfloat16 g_atth[BT * NE], g_attl[BT * NE];
__device__ float g_y1[BT * NE];
__device__ float g_xn2[BT * NE];
__device__ __nv_bfloat16 g_xn2h[BT * NE], g_xn2l[BT * NE];
__device__ __nv_bfloat16 g_hh[(long)BT * FF], g_hl[(long)BT * FF];
// transposed (N-major, K-contig) split weights
__device__ __nv_bfloat16 g_wqkvh[3 * NE * NE], g_wqkvl[3 * NE * NE];  // [3072][1024]
__device__ __nv_bfloat16 g_wph[NE * NE],  g_wpl[NE * NE];             // [1024][1024]
__device__ __nv_bfloat16 g_w1h[FF * NE],  g_w1l[FF * NE];             // [4096][1024]
__device__ __nv_bfloat16 g_w2h[NE * FF],  g_w2l[NE * FF];             // [1024][4096]

// ---------------- helpers ----------------
__device__ __forceinline__ uint32_t smem_u32(const void* p) {
    uint32_t a;
    asm("{ .reg .u64 t; cvta.to.shared.u64 t, %1; cvt.u32.u64 %0, t; }"
        : "=r"(a) : "l"(p));
    return a;
}
__device__ __forceinline__ void splitf(float v, __nv_bfloat16& h, __nv_bfloat16& l) {
    h = __float2bfloat16(v);
    l = __float2bfloat16(v - __bfloat162float(h));
}
__device__ __forceinline__ void cp16(uint32_t dst, const void* src) {
    asm volatile("cp.async.ca.shared.global [%0], [%1], 16;"
                 :: "r"(dst), "l"(src) : "memory");
}
__device__ __forceinline__ void cp_commit() {
    asm volatile("cp.async.commit_group;" ::: "memory");
}
template <int N>
__device__ __forceinline__ void cp_wait() {
    asm volatile("cp.async.wait_group %0;" :: "n"(N) : "memory");
}
__device__ __forceinline__ void mma16816(float* c, const uint32_t* a,
                                         const uint32_t* b) {
    asm volatile(
        "mma.sync.aligned.m16n8k16.row.col.f32.bf16.bf16.f32 "
        "{%0,%1,%2,%3}, {%4,%5,%6,%7}, {%8,%9}, {%0,%1,%2,%3};"
        : "+f"(c[0]), "+f"(c[1]), "+f"(c[2]), "+f"(c[3])
        : "r"(a[0]), "r"(a[1]), "r"(a[2]), "r"(a[3]), "r"(b[0]), "r"(b[1]));
}
__device__ __forceinline__ void ldsm4(uint32_t* r, uint32_t addr) {
    asm volatile("ldmatrix.sync.aligned.m8n8.x4.shared.b16 {%0,%1,%2,%3}, [%4];"
                 : "=r"(r[0]), "=r"(r[1]), "=r"(r[2]), "=r"(r[3]) : "r"(addr));
}

// ---------------- layernorm: fp32 out + bf16 hi/lo out ----------------
__global__ __launch_bounds__(256) void ln_kernel(const float* __restrict__ x,
                                                 const float* __restrict__ g,
                                                 const float* __restrict__ be,
                                                 float* __restrict__ y,
                                                 __nv_bfloat16* __restrict__ yh,
                                                 __nv_bfloat16* __restrict__ yl) {
    __shared__ float sred[16];
    long row = blockIdx.x;
    const float4* xr = (const float4*)(x + row * NE);
    int tid = threadIdx.x;
    float4 t = xr[tid];
    float s  = t.x + t.y + t.z + t.w;
    float s2 = t.x * t.x + t.y * t.y + t.z * t.z + t.w * t.w;
    #pragma unroll
    for (int o = 16; o; o >>= 1) {
        s  += __shfl_xor_sync(0xffffffffu, s,  o);
        s2 += __shfl_xor_sync(0xffffffffu, s2, o);
    }
    int w = tid >> 5;
    if ((tid & 31) == 0) { sred[w] = s; sred[8 + w] = s2; }
    __syncthreads();
    if (tid < 32) {
        float a  = (tid < 8) ? sred[tid]     : 0.f;
        float a2 = (tid < 8) ? sred[8 + tid] : 0.f;
        #pragma unroll
        for (int o = 4; o; o >>= 1) {
            a  += __shfl_xor_sync(0xffffffffu, a,  o);
            a2 += __shfl_xor_sync(0xffffffffu, a2, o);
        }
        if (tid == 0) { sred[0] = a; sred[1] = a2; }
    }
    __syncthreads();
    float mean = sred[0] * (1.f / NE);
    float var  = sred[1] * (1.f / NE) - mean * mean;
    float rstd = rsqrtf(var + 1e-5f);
    float4 gg = ((const float4*)g)[tid];
    float4 bb = ((const float4*)be)[tid];
    float4 o;
    o.x = (t.x - mean) * rstd * gg.x + bb.x;
    o.y = (t.y - mean) * rstd * gg.y + bb.y;
    o.z = (t.z - mean) * rstd * gg.z + bb.z;
    o.w = (t.w - mean) * rstd * gg.w + bb.w;
    ((float4*)(y + row * NE))[tid] = o;
    __nv_bfloat16 h0, l0, h1, l1, h2, l2, h3, l3;
    splitf(o.x, h0, l0); splitf(o.y, h1, l1);
    splitf(o.z, h2, l2); splitf(o.w, h3, l3);
    __nv_bfloat162 H0; H0.x = h0; H0.y = h1;
    __nv_bfloat162 H1; H1.x = h2; H1.y = h3;
    __nv_bfloat162 L0; L0.x = l0; L0.y = l1;
    __nv_bfloat162 L1; L1.x = l2; L1.y = l3;
    __nv_bfloat162* ph = (__nv_bfloat162*)(yh + row * NE);
    __nv_bfloat162* pl = (__nv_bfloat162*)(yl + row * NE);
    ph[tid * 2] = H0; ph[tid * 2 + 1] = H1;
    pl[tid * 2] = L0; pl[tid * 2 + 1] = L1;
}

// ---------------- weight prep: transpose + bf16 split ----------------
__global__ __launch_bounds__(256) void tconv_kernel(const float* __restrict__ src,
                                                    __nv_bfloat16* __restrict__ dh,
                                                    __nv_bfloat16* __restrict__ dl,
                                                    int R, int C, int RS, int RO) {
    __shared__ float tile[32][33];
    int tx = threadIdx.x, ty = threadIdx.y;
    int x0 = blockIdx.x * 32, y0 = blockIdx.y * 32;
    #pragma unroll
    for (int i = 0; i < 4; i++)
        tile[ty + 8 * i][tx] = src[(long)(y0 + ty + 8 * i) * C + x0 + tx];
    __syncthreads();
    #pragma unroll
    for (int i = 0; i < 4; i++) {
        int c = x0 + ty + 8 * i;
        float v = tile[tx][ty + 8 * i];
        __nv_bfloat16 h, l; splitf(v, h, l);
        long di = (long)(RO + c) * RS + y0 + tx;
        dh[di] = h; dl[di] = l;
    }
}
__global__ __launch_bounds__(256) void qkv_prep_kernel(const float* __restrict__ wq,
                                                       const float* __restrict__ wk,
                                                       const float* __restrict__ wv,
                                                       __nv_bfloat16* __restrict__ dh,
                                                       __nv_bfloat16* __restrict__ dl) {
    __shared__ float tile[32][33];
    int z = blockIdx.z, which = z >> 4, h = z & 15;
    const float* src = ((which == 0) ? wq : (which == 1) ? wk : wv) + (long)h * NE * HS;
    int RO = which * NE + h * HS;
    int tx = threadIdx.x, ty = threadIdx.y;
    int x0 = blockIdx.x * 32, y0 = blockIdx.y * 32;
    #pragma unroll
    for (int i = 0; i < 4; i++)
        tile[ty + 8 * i][tx] = src[(long)(y0 + ty + 8 * i) * HS + x0 + tx];
    __syncthreads();
    #pragma unroll
    for (int i = 0; i < 4; i++) {
        int c = x0 + ty + 8 * i;
        float v = tile[tx][ty + 8 * i];
        __nv_bfloat16 hh, ll; splitf(v, hh, ll);
        long di = (long)(RO + c) * NE + y0 + tx;
        dh[di] = hh; dl[di] = ll;
    }
}

// ---------------- warp-MMA split-bf16 GEMM (ldmatrix + 2-stage, 2 CTA/SM) ---
// C[M, Ndim] = (Ah+Al)[M,K] @ (Bh+Bl)[Ndim,K]^T, 3-term split, fp32 accum.
// CTA tile 128x128, 8 warps (4m x 2n), warp tile 32x64, K-chunk 32.
// Inner loop = R7's measured-best form (volatile, interleaved per-acc order).
#define KC 32
#define ROWB 80                       // bytes per smem row (32 bf16 + pad)
#define MATB (128 * ROWB)             // 10240 B per matrix tile
#define STAGEB (4 * MATB)             // 40960 B per stage
#define SMTOT (2 * STAGEB)            // 81920 B -> 2 CTAs/SM

__global__ __launch_bounds__(256, 2) void mma_gemm(
    const __nv_bfloat16* __restrict__ Ah, const __nv_bfloat16* __restrict__ Al,
    const __nv_bfloat16* __restrict__ Bh, const __nv_bfloat16* __restrict__ Bl,
    int Kdim, int Ndim,
    const float* __restrict__ bias, const float* __restrict__ res,
    float* __restrict__ Cf,
    __nv_bfloat16* __restrict__ Ch, __nv_bfloat16* __restrict__ Cl,
    float* __restrict__ Qo, float* __restrict__ Ko, float* __restrict__ Vo,
    int mode) {
    extern __shared__ char smem[];
    uint32_t sb = smem_u32(smem);
    int tid = threadIdx.x;
    int wid = tid >> 5, lane = tid & 31;
    int warp_m = wid & 3, warp_n = wid >> 2;   // 4 x 2
    int r4 = lane >> 2, qp = lane & 3;
    int m0 = blockIdx.y * 128, n0 = blockIdx.x * 128;

    // per-lane ldmatrix base offsets (within a stage)
    uint32_t a_off = (uint32_t)(warp_m * 32 + (lane & 15)) * ROWB + ((lane >> 4) << 4);
    uint32_t b_off = (uint32_t)(warp_n * 64 + ((lane >> 4) << 3) + (lane & 7)) * ROWB
                     + (((lane >> 3) & 1) << 4);

    float acc[2][8][4];
    #pragma unroll
    for (int mt = 0; mt < 2; mt++)
        #pragma unroll
        for (int nt = 0; nt < 8; nt++)
            #pragma unroll
            for (int e = 0; e < 4; e++) acc[mt][nt][e] = 0.f;

    int nch = Kdim / KC;

    auto issue = [&](int c, int st) {
        int k0 = c * KC;
        uint32_t sbase = sb + st * STAGEB;
        #pragma unroll
        for (int j = 0; j < 8; j++) {
            int i = tid + j * 256;            // 0..2047
            int mat = i >> 9;                 // 0..3
            int rem = i & 511;
            int r = rem >> 2, cc = rem & 3;   // row, 16B-chunk
            const __nv_bfloat16* base =
                (mat == 0) ? Ah : (mat == 1) ? Al : (mat == 2) ? Bh : Bl;
            long grow = (mat < 2) ? ((long)(m0 + r) * Kdim)
                                  : ((long)(n0 + r) * Kdim);
            cp16(sbase + mat * MATB + r * ROWB + cc * 16,
                 base + grow + k0 + cc * 8);
        }
        cp_commit();
    };

    issue(0, 0);
    for (int c = 0; c < nch; c++) {
        int st = c & 1;
        if (c + 1 < nch) { issue(c + 1, st ^ 1); cp_wait<1>(); }
        else             { cp_wait<0>(); }
        __syncthreads();

        uint32_t stage = sb + st * STAGEB;
        #pragma unroll
        for (int ks = 0; ks < 2; ks++) {
            uint32_t ko = ks * 32;            // 16 bf16 = 32B per k-step
            uint32_t ah[2][4], al[2][4], bh[4][4], bl[4][4];
            #pragma unroll
            for (int mt = 0; mt < 2; mt++) {
                uint32_t ra = stage + a_off + mt * (16 * ROWB) + ko;
                ldsm4(ah[mt], ra);
                ldsm4(al[mt], ra + MATB);
            }
            #pragma unroll
            for (int np = 0; np < 4; np++) {
                uint32_t rb = stage + 2 * MATB + b_off + np * (16 * ROWB) + ko;
                ldsm4(bh[np], rb);
                ldsm4(bl[np], rb + MATB);
            }
            #pragma unroll
            for (int mt = 0; mt < 2; mt++)
                #pragma unroll
                for (int np = 0; np < 4; np++) {
                    mma16816(acc[mt][np * 2],     ah[mt], &bh[np][0]);
                    mma16816(acc[mt][np * 2],     ah[mt], &bl[np][0]);
                    mma16816(acc[mt][np * 2],     al[mt], &bh[np][0]);
                    mma16816(acc[mt][np * 2 + 1], ah[mt], &bh[np][2]);
                    mma16816(acc[mt][np * 2 + 1], ah[mt], &bl[np][2]);
                    mma16816(acc[mt][np * 2 + 1], al[mt], &bh[np][2]);
                }
        }
        __syncthreads();
    }

    // epilogue: c0,c1 at (r, n..n+1); c2,c3 at (r+8, n..n+1)
    #pragma unroll
    for (int mt = 0; mt < 2; mt++) {
        int gm0 = m0 + warp_m * 32 + mt * 16 + r4;
        #pragma unroll
        for (int nt = 0; nt < 8; nt++) {
            int gn = n0 + warp_n * 64 + nt * 8 + 2 * qp;
            #pragma unroll
            for (int half = 0; half < 2; half++) {
                long gm = gm0 + half * 8;
                float v0 = acc[mt][nt][half * 2];
                float v1 = acc[mt][nt][half * 2 + 1];
                if (mode == 1) {
                    int which = gn >> 10, hd = (gn >> 6) & 15, e = gn & 63;
                    float* basew = (which == 0) ? Qo : (which == 1) ? Ko : Vo;
                    float2 t; t.x = v0; t.y = v1;
                    *(float2*)(basew + ((long)hd * BT + gm) * HS + e) = t;
                } else if (mode == 2) {
                    v0 = fmaxf(v0 + bias[gn], 0.f);
                    v1 = fmaxf(v1 + bias[gn + 1], 0.f);
                    __nv_bfloat16 h0, l0, h1, l1;
                    splitf(v0, h0, l0); splitf(v1, h1, l1);
                    __nv_bfloat162 H; H.x = h0; H.y = h1;
                    __nv_bfloat162 L; L.x = l0; L.y = l1;
                    long idx = (gm * (long)Ndim + gn) >> 1;
                    ((__nv_bfloat162*)Ch)[idx] = H;
                    ((__nv_bfloat162*)Cl)[idx] = L;
                } else {
                    if (bias) { v0 += bias[gn]; v1 += bias[gn + 1]; }
                    if (res) {
                        float2 rr = *(const float2*)(res + gm * (long)Ndim + gn);
                        v0 += rr.x; v1 += rr.y;
                    }
                    float2 t; t.x = v0; t.y = v1;
                    *(float2*)(Cf + gm * (long)Ndim + gn) = t;
                }
            }
        }
    }
}

// ---------------- causal attention (fp32), bf16 hi/lo output ----------------
__global__ __launch_bounds__(128) void attn_kernel(const float* __restrict__ Q,
                                                   const float* __restrict__ K,
                                                   const float* __restrict__ V,
                                                   __nv_bfloat16* __restrict__ Oh,
                                                   __nv_bfloat16* __restrict__ Ol) {
    __shared__ float Ks[64][64];
    __shared__ float Vs[64][64];
    int q0 = blockIdx.x * 64;
    int h  = blockIdx.y;
    int b  = blockIdx.z;
    long base = ((long)h * BT + (long)b * TT) * HS;
    const float* Qp = Q + base;
    const float* Kp = K + base;
    const float* Vp = V + base;

    int tid = threadIdx.x, qi = tid >> 1, half = tid & 1;
    int tq = q0 + qi;

    float qreg[32], acc[32];
    #pragma unroll
    for (int e = 0; e < 32; e++) acc[e] = 0.f;
    {
        const float4* qrow = (const float4*)(Qp + (long)tq * HS + half * 32);
        #pragma unroll
        for (int e4 = 0; e4 < 8; e4++) {
            float4 t = qrow[e4];
            qreg[e4 * 4 + 0] = t.x; qreg[e4 * 4 + 1] = t.y;
            qreg[e4 * 4 + 2] = t.z; qreg[e4 * 4 + 3] = t.w;
        }
    }
    const float scale = 0.125f;
    float lsum = 0.f;

    for (int s0 = 0; s0 <= q0; s0 += 64) {
        __syncthreads();
        for (int i = tid; i < 64 * 16; i += 128) {
            int r = i >> 4, c4 = (i & 15) << 2;
            *(float4*)&Ks[r][c4] = *(const float4*)(Kp + (long)(s0 + r) * HS + c4);
            *(float4*)&Vs[r][c4] = *(const float4*)(Vp + (long)(s0 + r) * HS + c4);
        }
        __syncthreads();
        bool diag = (s0 == q0);
        #pragma unroll 4
        for (int j = 0; j < 64; j++) {
            float s = 0.f;
            const float* kr = &Ks[j][half * 32];
            #pragma unroll
            for (int e = 0; e < 32; e++) s = fmaf(qreg[e], kr[e], s);
            s += __shfl_xor_sync(0xffffffffu, s, 1);
            s *= scale;
            float pe = (!diag || (s0 + j <= tq)) ? __expf(s) : 0.f;
            lsum += pe;
            const float* vr = &Vs[j][half * 32];
            #pragma unroll
            for (int e = 0; e < 32; e++) acc[e] = fmaf(pe, vr[e], acc[e]);
        }
    }
    float inv = 1.f / lsum;
    long ocol = (long)(b * TT + tq) * NE + h * HS + half * 32;
    __nv_bfloat162* ph = (__nv_bfloat162*)(Oh + ocol);
    __nv_bfloat162* pl = (__nv_bfloat162*)(Ol + ocol);
    #pragma unroll
    for (int e2 = 0; e2 < 16; e2++) {
        float v0 = acc[e2 * 2] * inv, v1 = acc[e2 * 2 + 1] * inv;
        __nv_bfloat16 h0, l0, h1, l1;
        splitf(v0, h0, l0); splitf(v1, h1, l1);
        __nv_bfloat162 H; H.x = h0; H.y = h1;
        __nv_bfloat162 L; L.x = l0; L.y = l1;
        ph[e2] = H; pl[e2] = L;
    }
}

// ---------------- launch ----------------
extern "C" void kernel_launch(void* const* d_in, const int* in_sizes, int n_in,
                              void* d_out, int out_size) {
    const float* x      = (const float*)d_in[0];
    const float* wq     = (const float*)d_in[1];
    const float* wk     = (const float*)d_in[2];
    const float* wv     = (const float*)d_in[3];
    const float* w_proj = (const float*)d_in[4];
    const float* b_proj = (const float*)d_in[5];
    const float* w1     = (const float*)d_in[6];
    const float* b1     = (const float*)d_in[7];
    const float* w2     = (const float*)d_in[8];
    const float* b2     = (const float*)d_in[9];
    const float* g1     = (const float*)d_in[10];
    const float* be1    = (const float*)d_in[11];
    const float* g2     = (const float*)d_in[12];
    const float* be2    = (const float*)d_in[13];
    float* out = (float*)d_out;

    float *xn1, *q, *k, *v, *y1, *xn2;
    __nv_bfloat16 *xn1h, *xn1l, *atth, *attl, *xn2h, *xn2l, *hh, *hl;
    __nv_bfloat16 *wqkvh, *wqkvl, *wph, *wpl, *w1h, *w1l, *w2h, *w2l;
    cudaGetSymbolAddress((void**)&xn1,  g_xn1);
    cudaGetSymbolAddress((void**)&xn1h, g_xn1h);
    cudaGetSymbolAddress((void**)&xn1l, g_xn1l);
    cudaGetSymbolAddress((void**)&q,    g_q);
    cudaGetSymbolAddress((void**)&k,    g_k);
    cudaGetSymbolAddress((void**)&v,    g_v);
    cudaGetSymbolAddress((void**)&atth, g_atth);
    cudaGetSymbolAddress((void**)&attl, g_attl);
    cudaGetSymbolAddress((void**)&y1,   g_y1);
    cudaGetSymbolAddress((void**)&xn2,  g_xn2);
    cudaGetSymbolAddress((void**)&xn2h, g_xn2h);
    cudaGetSymbolAddress((void**)&xn2l, g_xn2l);
    cudaGetSymbolAddress((void**)&hh,   g_hh);
    cudaGetSymbolAddress((void**)&hl,   g_hl);
    cudaGetSymbolAddress((void**)&wqkvh, g_wqkvh);
    cudaGetSymbolAddress((void**)&wqkvl, g_wqkvl);
    cudaGetSymbolAddress((void**)&wph,  g_wph);
    cudaGetSymbolAddress((void**)&wpl,  g_wpl);
    cudaGetSymbolAddress((void**)&w1h,  g_w1h);
    cudaGetSymbolAddress((void**)&w1l,  g_w1l);
    cudaGetSymbolAddress((void**)&w2h,  g_w2h);
    cudaGetSymbolAddress((void**)&w2l,  g_w2l);

    cudaFuncSetAttribute(mma_gemm, cudaFuncAttributeMaxDynamicSharedMemorySize, SMTOT);

    dim3 tb32(32, 8);
    // weight prep (transpose + split)
    qkv_prep_kernel<<<dim3(2, 32, 48), tb32>>>(wq, wk, wv, wqkvh, wqkvl);
    tconv_kernel<<<dim3(32, 32), tb32>>>(w_proj, wph, wpl, NE, NE, NE, 0);
    tconv_kernel<<<dim3(128, 32), tb32>>>(w1, w1h, w1l, NE, FF, NE, 0);
    tconv_kernel<<<dim3(32, 128), tb32>>>(w2, w2h, w2l, FF, NE, FF, 0);

    // 1) layernorm1
    ln_kernel<<<BT, 256>>>(x, g1, be1, xn1, xn1h, xn1l);

    // 2) fused QKV: [8192,1024] @ WTqkv[3072,1024]^T, scatter to q/k/v
    mma_gemm<<<dim3(24, 64), 256, SMTOT>>>(xn1h, xn1l, wqkvh, wqkvl, NE, 3 * NE,
                                           nullptr, nullptr, nullptr, nullptr, nullptr,
                                           q, k, v, 1);
    // 3) attention (fp32 in, bf16 hi/lo out)
    attn_kernel<<<dim3(TT / 64, NH, BD), 128>>>(q, k, v, atth, attl);

    // 4) proj + bias + residual(xn1) -> y1
    mma_gemm<<<dim3(8, 64), 256, SMTOT>>>(atth, attl, wph, wpl, NE, NE,
                                          b_proj, xn1, y1, nullptr, nullptr,
                                          nullptr, nullptr, nullptr, 0);
    // 5) layernorm2
    ln_kernel<<<BT, 256>>>(y1, g2, be2, xn2, xn2h, xn2l);

    // 6) FFN1 + bias + relu -> h (bf16 hi/lo)
    mma_gemm<<<dim3(32, 64), 256, SMTOT>>>(xn2h, xn2l, w1h, w1l, NE, FF,
                                           b1, nullptr, nullptr, hh, hl,
                                           nullptr, nullptr, nullptr, 2);
    // 7) FFN2 + bias + residual(xn2) -> out
    mma_gemm<<<dim3(8, 64), 256, SMTOT>>>(hh, hl, w2h, w2l, FF, NE,
                                          b2, xn2, out, nullptr, nullptr,
                                          nullptr, nullptr, nullptr, 0);
}

// round 12
// speedup vs baseline: 2.5405x; 1.4950x over previous
#include <cuda_runtime.h>
#include <cuda_bf16.h>
#include <stdint.h>
#include <math.h>

#define BD 8
#define TT 1024
#define NE 1024
#define NH 16
#define HS 64
#define BT (BD * TT)     // 8192
#define FF (4 * NE)      // 4096

// ---------------- scratch (alloc-guard-safe device globals) ----------------
__device__ float g_xn1[BT * NE];
__device__ __nv_bfloat16 g_xn1h[BT * NE], g_xn1l[BT * NE];
__device__ __nv_bfloat16 g_qh[NH * BT * HS], g_ql[NH * BT * HS];
__device__ __nv_bfloat16 g_kh[NH * BT * HS], g_kl[NH * BT * HS];
__device__ float g_v[NH * BT * HS];
__device__ __nv_bfloat16 g_vth[NH * BT * HS], g_vtl[NH * BT * HS];  // [h][b][e][t]
__device__ __nv_bfloat16 g_atth[BT * NE], g_attl[BT * NE];
__device__ float g_y1[BT * NE];
__device__ float g_xn2[BT * NE];
__device__ __nv_bfloat16 g_xn2h[BT * NE], g_xn2l[BT * NE];
__device__ __nv_bfloat16 g_hh[(long)BT * FF], g_hl[(long)BT * FF];
__device__ __nv_bfloat16 g_wqkvh[3 * NE * NE], g_wqkvl[3 * NE * NE];
__device__ __nv_bfloat16 g_wph[NE * NE],  g_wpl[NE * NE];
__device__ __nv_bfloat16 g_w1h[FF * NE],  g_w1l[FF * NE];
__device__ __nv_bfloat16 g_w2h[NE * FF],  g_w2l[NE * FF];

// ---------------- helpers ----------------
__device__ __forceinline__ uint32_t smem_u32(const void* p) {
    uint32_t a;
    asm("{ .reg .u64 t; cvta.to.shared.u64 t, %1; cvt.u32.u64 %0, t; }"
        : "=r"(a) : "l"(p));
    return a;
}
__device__ __forceinline__ void splitf(float v, __nv_bfloat16& h, __nv_bfloat16& l) {
    h = __float2bfloat16(v);
    l = __float2bfloat16(v - __bfloat162float(h));
}
__device__ __forceinline__ void cp16(uint32_t dst, const void* src) {
    asm volatile("cp.async.ca.shared.global [%0], [%1], 16;"
                 :: "r"(dst), "l"(src) : "memory");
}
__device__ __forceinline__ void cp_commit() {
    asm volatile("cp.async.commit_group;" ::: "memory");
}
template <int N>
__device__ __forceinline__ void cp_wait() {
    asm volatile("cp.async.wait_group %0;" :: "n"(N) : "memory");
}
__device__ __forceinline__ void mma16816(float* c, const uint32_t* a,
                                         const uint32_t* b) {
    asm volatile(
        "mma.sync.aligned.m16n8k16.row.col.f32.bf16.bf16.f32 "
        "{%0,%1,%2,%3}, {%4,%5,%6,%7}, {%8,%9}, {%0,%1,%2,%3};"
        : "+f"(c[0]), "+f"(c[1]), "+f"(c[2]), "+f"(c[3])
        : "r"(a[0]), "r"(a[1]), "r"(a[2]), "r"(a[3]), "r"(b[0]), "r"(b[1]));
}
__device__ __forceinline__ void ldsm4(uint32_t* r, uint32_t addr) {
    asm volatile("ldmatrix.sync.aligned.m8n8.x4.shared.b16 {%0,%1,%2,%3}, [%4];"
                 : "=r"(r[0]), "=r"(r[1]), "=r"(r[2]), "=r"(r[3]) : "r"(addr));
}

// ---------------- layernorm: fp32 out + bf16 hi/lo out ----------------
__global__ __launch_bounds__(256) void ln_kernel(const float* __restrict__ x,
                                                 const float* __restrict__ g,
                                                 const float* __restrict__ be,
                                                 float* __restrict__ y,
                                                 __nv_bfloat16* __restrict__ yh,
                                                 __nv_bfloat16* __restrict__ yl) {
    __shared__ float sred[16];
    long row = blockIdx.x;
    const float4* xr = (const float4*)(x + row * NE);
    int tid = threadIdx.x;
    float4 t = xr[tid];
    float s  = t.x + t.y + t.z + t.w;
    float s2 = t.x * t.x + t.y * t.y + t.z * t.z + t.w * t.w;
    #pragma unroll
    for (int o = 16; o; o >>= 1) {
        s  += __shfl_xor_sync(0xffffffffu, s,  o);
        s2 += __shfl_xor_sync(0xffffffffu, s2, o);
    }
    int w = tid >> 5;
    if ((tid & 31) == 0) { sred[w] = s; sred[8 + w] = s2; }
    __syncthreads();
    if (tid < 32) {
        float a  = (tid < 8) ? sred[tid]     : 0.f;
        float a2 = (tid < 8) ? sred[8 + tid] : 0.f;
        #pragma unroll
        for (int o = 4; o; o >>= 1) {
            a  += __shfl_xor_sync(0xffffffffu, a,  o);
            a2 += __shfl_xor_sync(0xffffffffu, a2, o);
        }
        if (tid == 0) { sred[0] = a; sred[1] = a2; }
    }
    __syncthreads();
    float mean = sred[0] * (1.f / NE);
    float var  = sred[1] * (1.f / NE) - mean * mean;
    float rstd = rsqrtf(var + 1e-5f);
    float4 gg = ((const float4*)g)[tid];
    float4 bb = ((const float4*)be)[tid];
    float4 o;
    o.x = (t.x - mean) * rstd * gg.x + bb.x;
    o.y = (t.y - mean) * rstd * gg.y + bb.y;
    o.z = (t.z - mean) * rstd * gg.z + bb.z;
    o.w = (t.w - mean) * rstd * gg.w + bb.w;
    ((float4*)(y + row * NE))[tid] = o;
    __nv_bfloat16 h0, l0, h1, l1, h2, l2, h3, l3;
    splitf(o.x, h0, l0); splitf(o.y, h1, l1);
    splitf(o.z, h2, l2); splitf(o.w, h3, l3);
    __nv_bfloat162 H0; H0.x = h0; H0.y = h1;
    __nv_bfloat162 H1; H1.x = h2; H1.y = h3;
    __nv_bfloat162 L0; L0.x = l0; L0.y = l1;
    __nv_bfloat162 L1; L1.x = l2; L1.y = l3;
    __nv_bfloat162* ph = (__nv_bfloat162*)(yh + row * NE);
    __nv_bfloat162* pl = (__nv_bfloat162*)(yl + row * NE);
    ph[tid * 2] = H0; ph[tid * 2 + 1] = H1;
    pl[tid * 2] = L0; pl[tid * 2 + 1] = L1;
}

// ---------------- weight prep: transpose + bf16 split ----------------
__global__ __launch_bounds__(256) void tconv_kernel(const float* __restrict__ src,
                                                    __nv_bfloat16* __restrict__ dh,
                                                    __nv_bfloat16* __restrict__ dl,
                                                    int R, int C, int RS, int RO) {
    __shared__ float tile[32][33];
    int tx = threadIdx.x, ty = threadIdx.y;
    int x0 = blockIdx.x * 32, y0 = blockIdx.y * 32;
    #pragma unroll
    for (int i = 0; i < 4; i++)
        tile[ty + 8 * i][tx] = src[(long)(y0 + ty + 8 * i) * C + x0 + tx];
    __syncthreads();
    #pragma unroll
    for (int i = 0; i < 4; i++) {
        int c = x0 + ty + 8 * i;
        float v = tile[tx][ty + 8 * i];
        __nv_bfloat16 h, l; splitf(v, h, l);
        long di = (long)(RO + c) * RS + y0 + tx;
        dh[di] = h; dl[di] = l;
    }
}
__global__ __launch_bounds__(256) void qkv_prep_kernel(const float* __restrict__ wq,
                                                       const float* __restrict__ wk,
                                                       const float* __restrict__ wv,
                                                       __nv_bfloat16* __restrict__ dh,
                                                       __nv_bfloat16* __restrict__ dl) {
    __shared__ float tile[32][33];
    int z = blockIdx.z, which = z >> 4, h = z & 15;
    const float* src = ((which == 0) ? wq : (which == 1) ? wk : wv) + (long)h * NE * HS;
    int RO = which * NE + h * HS;
    int tx = threadIdx.x, ty = threadIdx.y;
    int x0 = blockIdx.x * 32, y0 = blockIdx.y * 32;
    #pragma unroll
    for (int i = 0; i < 4; i++)
        tile[ty + 8 * i][tx] = src[(long)(y0 + ty + 8 * i) * HS + x0 + tx];
    __syncthreads();
    #pragma unroll
    for (int i = 0; i < 4; i++) {
        int c = x0 + ty + 8 * i;
        float v = tile[tx][ty + 8 * i];
        __nv_bfloat16 hh, ll; splitf(v, hh, ll);
        long di = (long)(RO + c) * NE + y0 + tx;
        dh[di] = hh; dl[di] = ll;
    }
}

// ---------------- V transpose + split: [h][bt][e] fp32 -> [h][b][e][t] bf16 h/l
__global__ __launch_bounds__(256) void vt_prep(const float* __restrict__ V,
                                               __nv_bfloat16* __restrict__ dh,
                                               __nv_bfloat16* __restrict__ dl) {
    __shared__ float tile[32][33];
    int z = blockIdx.z, h = z >> 3, b = z & 7;
    int t0 = blockIdx.x * 32, e0 = blockIdx.y * 32;
    int tx = threadIdx.x, ty = threadIdx.y;
    long ibase = ((long)h * BT + (long)b * TT) * HS;
    #pragma unroll
    for (int i = 0; i < 4; i++)
        tile[ty + 8 * i][tx] = V[ibase + (long)(t0 + ty + 8 * i) * HS + e0 + tx];
    __syncthreads();
    long obase = (long)(h * BD + b) * HS * TT;
    #pragma unroll
    for (int i = 0; i < 4; i++) {
        int e = e0 + ty + 8 * i;
        float v = tile[tx][ty + 8 * i];
        __nv_bfloat16 hh, ll; splitf(v, hh, ll);
        long di = obase + (long)e * TT + t0 + tx;
        dh[di] = hh; dl[di] = ll;
    }
}

// ---------------- warp-MMA split-bf16 GEMM (R11 best config) ----------------
#define KC 32
#define ROWB 80
#define MATB (128 * ROWB)
#define STAGEB (4 * MATB)
#define SMTOT (2 * STAGEB)

__global__ __launch_bounds__(256, 2) void mma_gemm(
    const __nv_bfloat16* __restrict__ Ah, const __nv_bfloat16* __restrict__ Al,
    const __nv_bfloat16* __restrict__ Bh, const __nv_bfloat16* __restrict__ Bl,
    int Kdim, int Ndim,
    const float* __restrict__ bias, const float* __restrict__ res,
    float* __restrict__ Cf,
    __nv_bfloat16* __restrict__ Ch, __nv_bfloat16* __restrict__ Cl,
    __nv_bfloat16* __restrict__ Kh2, __nv_bfloat16* __restrict__ Kl2,
    float* __restrict__ Vo,
    int mode) {
    extern __shared__ char smem[];
    uint32_t sb = smem_u32(smem);
    int tid = threadIdx.x;
    int wid = tid >> 5, lane = tid & 31;
    int warp_m = wid & 3, warp_n = wid >> 2;
    int r4 = lane >> 2, qp = lane & 3;
    int m0 = blockIdx.y * 128, n0 = blockIdx.x * 128;

    uint32_t a_off = (uint32_t)(warp_m * 32 + (lane & 15)) * ROWB + ((lane >> 4) << 4);
    uint32_t b_off = (uint32_t)(warp_n * 64 + ((lane >> 4) << 3) + (lane & 7)) * ROWB
                     + (((lane >> 3) & 1) << 4);

    float acc[2][8][4];
    #pragma unroll
    for (int mt = 0; mt < 2; mt++)
        #pragma unroll
        for (int nt = 0; nt < 8; nt++)
            #pragma unroll
            for (int e = 0; e < 4; e++) acc[mt][nt][e] = 0.f;

    int nch = Kdim / KC;

    auto issue = [&](int c, int st) {
        int k0 = c * KC;
        uint32_t sbase = sb + st * STAGEB;
        #pragma unroll
        for (int j = 0; j < 8; j++) {
            int i = tid + j * 256;
            int mat = i >> 9;
            int rem = i & 511;
            int r = rem >> 2, cc = rem & 3;
            const __nv_bfloat16* base =
                (mat == 0) ? Ah : (mat == 1) ? Al : (mat == 2) ? Bh : Bl;
            long grow = (mat < 2) ? ((long)(m0 + r) * Kdim)
                                  : ((long)(n0 + r) * Kdim);
            cp16(sbase + mat * MATB + r * ROWB + cc * 16,
                 base + grow + k0 + cc * 8);
        }
        cp_commit();
    };

    issue(0, 0);
    for (int c = 0; c < nch; c++) {
        int st = c & 1;
        if (c + 1 < nch) { issue(c + 1, st ^ 1); cp_wait<1>(); }
        else             { cp_wait<0>(); }
        __syncthreads();

        uint32_t stage = sb + st * STAGEB;
        #pragma unroll
        for (int ks = 0; ks < 2; ks++) {
            uint32_t ko = ks * 32;
            uint32_t ah[2][4], al[2][4], bh[4][4], bl[4][4];
            #pragma unroll
            for (int mt = 0; mt < 2; mt++) {
                uint32_t ra = stage + a_off + mt * (16 * ROWB) + ko;
                ldsm4(ah[mt], ra);
                ldsm4(al[mt], ra + MATB);
            }
            #pragma unroll
            for (int np = 0; np < 4; np++) {
                uint32_t rb = stage + 2 * MATB + b_off + np * (16 * ROWB) + ko;
                ldsm4(bh[np], rb);
                ldsm4(bl[np], rb + MATB);
            }
            #pragma unroll
            for (int mt = 0; mt < 2; mt++)
                #pragma unroll
                for (int np = 0; np < 4; np++) {
                    mma16816(acc[mt][np * 2],     ah[mt], &bh[np][0]);
                    mma16816(acc[mt][np * 2],     ah[mt], &bl[np][0]);
                    mma16816(acc[mt][np * 2],     al[mt], &bh[np][0]);
                    mma16816(acc[mt][np * 2 + 1], ah[mt], &bh[np][2]);
                    mma16816(acc[mt][np * 2 + 1], ah[mt], &bl[np][2]);
                    mma16816(acc[mt][np * 2 + 1], al[mt], &bh[np][2]);
                }
        }
        __syncthreads();
    }

    #pragma unroll
    for (int mt = 0; mt < 2; mt++) {
        int gm0 = m0 + warp_m * 32 + mt * 16 + r4;
        #pragma unroll
        for (int nt = 0; nt < 8; nt++) {
            int gn = n0 + warp_n * 64 + nt * 8 + 2 * qp;
            #pragma unroll
            for (int half = 0; half < 2; half++) {
                long gm = gm0 + half * 8;
                float v0 = acc[mt][nt][half * 2];
                float v1 = acc[mt][nt][half * 2 + 1];
                if (mode == 1) {
                    int which = gn >> 10, hd = (gn >> 6) & 15, e = gn & 63;
                    long idx = ((long)hd * BT + gm) * HS + e;
                    if (which == 2) {
                        float2 t; t.x = v0; t.y = v1;
                        *(float2*)(Vo + idx) = t;
                    } else {
                        __nv_bfloat16 h0, l0, h1, l1;
                        splitf(v0, h0, l0); splitf(v1, h1, l1);
                        __nv_bfloat162 H; H.x = h0; H.y = h1;
                        __nv_bfloat162 L; L.x = l0; L.y = l1;
                        __nv_bfloat16* dh = (which == 0) ? Ch : Kh2;
                        __nv_bfloat16* dl = (which == 0) ? Cl : Kl2;
                        *(__nv_bfloat162*)(dh + idx) = H;
                        *(__nv_bfloat162*)(dl + idx) = L;
                    }
                } else if (mode == 2) {
                    v0 = fmaxf(v0 + bias[gn], 0.f);
                    v1 = fmaxf(v1 + bias[gn + 1], 0.f);
                    __nv_bfloat16 h0, l0, h1, l1;
                    splitf(v0, h0, l0); splitf(v1, h1, l1);
                    __nv_bfloat162 H; H.x = h0; H.y = h1;
                    __nv_bfloat162 L; L.x = l0; L.y = l1;
                    long idx = (gm * (long)Ndim + gn) >> 1;
                    ((__nv_bfloat162*)Ch)[idx] = H;
                    ((__nv_bfloat162*)Cl)[idx] = L;
                } else {
                    if (bias) { v0 += bias[gn]; v1 += bias[gn + 1]; }
                    if (res) {
                        float2 rr = *(const float2*)(res + gm * (long)Ndim + gn);
                        v0 += rr.x; v1 += rr.y;
                    }
                    float2 t; t.x = v0; t.y = v1;
                    *(float2*)(Cf + gm * (long)Ndim + gn) = t;
                }
            }
        }
    }
}

// ---------------- tensor-core causal attention (split-bf16, flash-style) ----
// Q,K: bf16 h/l [h][bt][64]; Vt: bf16 h/l [h][b][e][t]; out bf16 h/l [bt][1024].
// Block: 64 queries, 128 threads (4 warps x 16 q-rows). No-max softmax.
#define AROW 144
#define ATILE (64 * AROW)              // 9216 B
#define SQ_H 0
#define SQ_L ATILE
#define SK_H (2 * ATILE)
#define SK_L (3 * ATILE)
#define SV_H (4 * ATILE)
#define SV_L (5 * ATILE)
#define ATT_SMEM (6 * ATILE)           // 55296 B

__global__ __launch_bounds__(128) void attn_mma(
    const __nv_bfloat16* __restrict__ Qh, const __nv_bfloat16* __restrict__ Ql,
    const __nv_bfloat16* __restrict__ Kh, const __nv_bfloat16* __restrict__ Kl,
    const __nv_bfloat16* __restrict__ Vth, const __nv_bfloat16* __restrict__ Vtl,
    __nv_bfloat16* __restrict__ Oh, __nv_bfloat16* __restrict__ Ol) {
    extern __shared__ char smem[];
    uint32_t sb = smem_u32(smem);
    int tid = threadIdx.x, wid = tid >> 5, lane = tid & 31;
    int r4 = lane >> 2, qp = lane & 3;
    int q0 = blockIdx.x * 64, h = blockIdx.y, b = blockIdx.z;
    long qk_base = ((long)h * BT + (long)b * TT) * HS;
    long vt_base = (long)(h * BD + b) * HS * TT;

    // stage Q tile (64 rows x 128B) h/l
    for (int i = tid; i < 64 * 8; i += 128) {
        int r = i >> 3, c = i & 7;
        long g = qk_base + (long)(q0 + r) * HS + c * 8;
        *(uint4*)(smem + SQ_H + r * AROW + c * 16) = *(const uint4*)(Qh + g);
        *(uint4*)(smem + SQ_L + r * AROW + c * 16) = *(const uint4*)(Ql + g);
    }
    __syncthreads();
    uint32_t a_off = (uint32_t)(wid * 16 + (lane & 15)) * AROW + ((lane >> 4) << 4);
    uint32_t qfh[4][4], qfl[4][4];
    #pragma unroll
    for (int kc = 0; kc < 4; kc++) {
        ldsm4(qfh[kc], sb + SQ_H + a_off + kc * 32);
        ldsm4(qfl[kc], sb + SQ_L + a_off + kc * 32);
    }

    uint32_t b_off = (uint32_t)(((lane >> 4) << 3) + (lane & 7)) * AROW
                     + (((lane >> 3) & 1) << 4);

    float o_acc[8][4];
    #pragma unroll
    for (int nt = 0; nt < 8; nt++)
        #pragma unroll
        for (int e = 0; e < 4; e++) o_acc[nt][e] = 0.f;
    float lsum0 = 0.f, lsum1 = 0.f;
    const float scale = 0.125f;
    int qrow0 = q0 + wid * 16 + r4;

    int ntiles = q0 / 64 + 1;
    for (int ti = 0; ti < ntiles; ti++) {
        int s0 = ti * 64;
        __syncthreads();
        for (int i = tid; i < 64 * 8; i += 128) {
            int r = i >> 3, c = i & 7;
            long gk = qk_base + (long)(s0 + r) * HS + c * 8;
            long gv = vt_base + (long)r * TT + s0 + c * 8;
            *(uint4*)(smem + SK_H + r * AROW + c * 16) = *(const uint4*)(Kh + gk);
            *(uint4*)(smem + SK_L + r * AROW + c * 16) = *(const uint4*)(Kl + gk);
            *(uint4*)(smem + SV_H + r * AROW + c * 16) = *(const uint4*)(Vth + gv);
            *(uint4*)(smem + SV_L + r * AROW + c * 16) = *(const uint4*)(Vtl + gv);
        }
        __syncthreads();

        // S = Q K^T, 3-term split
        float s_acc[8][4];
        #pragma unroll
        for (int nt = 0; nt < 8; nt++)
            #pragma unroll
            for (int e = 0; e < 4; e++) s_acc[nt][e] = 0.f;
        #pragma unroll
        for (int kc = 0; kc < 4; kc++) {
            uint32_t kbh[4][4], kbl[4][4];
            #pragma unroll
            for (int np = 0; np < 4; np++) {
                uint32_t rb = sb + b_off + np * (16 * AROW) + kc * 32;
                ldsm4(kbh[np], rb + SK_H);
                ldsm4(kbl[np], rb + SK_L);
            }
            #pragma unroll
            for (int np = 0; np < 4; np++) {
                mma16816(s_acc[np * 2],     qfh[kc], &kbh[np][0]);
                mma16816(s_acc[np * 2],     qfh[kc], &kbl[np][0]);
                mma16816(s_acc[np * 2],     qfl[kc], &kbh[np][0]);
                mma16816(s_acc[np * 2 + 1], qfh[kc], &kbh[np][2]);
                mma16816(s_acc[np * 2 + 1], qfh[kc], &kbl[np][2]);
                mma16816(s_acc[np * 2 + 1], qfl[kc], &kbh[np][2]);
            }
        }

        // softmax numerator + build P A-frags (C-frag == A-frag identity)
        bool diag = (s0 == q0);
        uint32_t pah[4][4], pal[4][4];
        #pragma unroll
        for (int nt = 0; nt < 8; nt++) {
            int scol = s0 + nt * 8 + 2 * qp;
            float e0 = (!diag || scol     <= qrow0)     ? __expf(s_acc[nt][0] * scale) : 0.f;
            float e1 = (!diag || scol + 1 <= qrow0)     ? __expf(s_acc[nt][1] * scale) : 0.f;
            float e2 = (!diag || scol     <= qrow0 + 8) ? __expf(s_acc[nt][2] * scale) : 0.f;
            float e3 = (!diag || scol + 1 <= qrow0 + 8) ? __expf(s_acc[nt][3] * scale) : 0.f;
            lsum0 += e0 + e1; lsum1 += e2 + e3;
            __nv_bfloat16 h0, l0, h1, l1, h2, l2, h3, l3;
            splitf(e0, h0, l0); splitf(e1, h1, l1);
            splitf(e2, h2, l2); splitf(e3, h3, l3);
            __nv_bfloat162 H01; H01.x = h0; H01.y = h1;
            __nv_bfloat162 H23; H23.x = h2; H23.y = h3;
            __nv_bfloat162 L01; L01.x = l0; L01.y = l1;
            __nv_bfloat162 L23; L23.x = l2; L23.y = l3;
            int j = nt >> 1, hf = (nt & 1) * 2;
            pah[j][hf]     = *(uint32_t*)&H01;
            pah[j][hf + 1] = *(uint32_t*)&H23;
            pal[j][hf]     = *(uint32_t*)&L01;
            pal[j][hf + 1] = *(uint32_t*)&L23;
        }

        // O += P V  (B = V^T rows [e][s], 3-term split)
        #pragma unroll
        for (int kc = 0; kc < 4; kc++) {
            uint32_t vbh[4][4], vbl[4][4];
            #pragma unroll
            for (int np = 0; np < 4; np++) {
                uint32_t rb = sb + b_off + np * (16 * AROW) + kc * 32;
                ldsm4(vbh[np], rb + SV_H);
                ldsm4(vbl[np], rb + SV_L);
            }
            #pragma unroll
            for (int np = 0; np < 4; np++) {
                mma16816(o_acc[np * 2],     pah[kc], &vbh[np][0]);
                mma16816(o_acc[np * 2],     pah[kc], &vbl[np][0]);
                mma16816(o_acc[np * 2],     pal[kc], &vbh[np][0]);
                mma16816(o_acc[np * 2 + 1], pah[kc], &vbh[np][2]);
                mma16816(o_acc[np * 2 + 1], pah[kc], &vbl[np][2]);
                mma16816(o_acc[np * 2 + 1], pal[kc], &vbh[np][2]);
            }
        }
    }

    lsum0 += __shfl_xor_sync(0xffffffffu, lsum0, 1);
    lsum0 += __shfl_xor_sync(0xffffffffu, lsum0, 2);
    lsum1 += __shfl_xor_sync(0xffffffffu, lsum1, 1);
    lsum1 += __shfl_xor_sync(0xffffffffu, lsum1, 2);
    float inv0 = 1.f / lsum0, inv1 = 1.f / lsum1;

    #pragma unroll
    for (int nt = 0; nt < 8; nt++) {
        int e = nt * 8 + 2 * qp;
        long i0 = ((long)(b * TT) + qrow0) * NE + h * HS + e;
        long i1 = i0 + 8L * NE;
        float v0 = o_acc[nt][0] * inv0, v1 = o_acc[nt][1] * inv0;
        float v2 = o_acc[nt][2] * inv1, v3 = o_acc[nt][3] * inv1;
        __nv_bfloat16 h0, l0, h1, l1; splitf(v0, h0, l0); splitf(v1, h1, l1);
        __nv_bfloat162 H; H.x = h0; H.y = h1;
        __nv_bfloat162 L; L.x = l0; L.y = l1;
        *(__nv_bfloat162*)(Oh + i0) = H;
        *(__nv_bfloat162*)(Ol + i0) = L;
        __nv_bfloat16 h2, l2, h3, l3; splitf(v2, h2, l2); splitf(v3, h3, l3);
        __nv_bfloat162 H2; H2.x = h2; H2.y = h3;
        __nv_bfloat162 L2; L2.x = l2; L2.y = l3;
        *(__nv_bfloat162*)(Oh + i1) = H2;
        *(__nv_bfloat162*)(Ol + i1) = L2;
    }
}

// ---------------- launch ----------------
extern "C" void kernel_launch(void* const* d_in, const int* in_sizes, int n_in,
                              void* d_out, int out_size) {
    const float* x      = (const float*)d_in[0];
    const float* wq     = (const float*)d_in[1];
    const float* wk     = (const float*)d_in[2];
    const float* wv     = (const float*)d_in[3];
    const float* w_proj = (const float*)d_in[4];
    const float* b_proj = (const float*)d_in[5];
    const float* w1     = (const float*)d_in[6];
    const float* b1     = (const float*)d_in[7];
    const float* w2     = (const float*)d_in[8];
    const float* b2     = (const float*)d_in[9];
    const float* g1     = (const float*)d_in[10];
    const float* be1    = (const float*)d_in[11];
    const float* g2     = (const float*)d_in[12];
    const float* be2    = (const float*)d_in[13];
    float* out = (float*)d_out;

    float *xn1, *v, *y1, *xn2;
    __nv_bfloat16 *xn1h, *xn1l, *qh, *ql, *kh, *kl, *vth, *vtl;
    __nv_bfloat16 *atth, *attl, *xn2h, *xn2l, *hh, *hl;
    __nv_bfloat16 *wqkvh, *wqkvl, *wph, *wpl, *w1h, *w1l, *w2h, *w2l;
    cudaGetSymbolAddress((void**)&xn1,  g_xn1);
    cudaGetSymbolAddress((void**)&xn1h, g_xn1h);
    cudaGetSymbolAddress((void**)&xn1l, g_xn1l);
    cudaGetSymbolAddress((void**)&qh,   g_qh);
    cudaGetSymbolAddress((void**)&ql,   g_ql);
    cudaGetSymbolAddress((void**)&kh,   g_kh);
    cudaGetSymbolAddress((void**)&kl,   g_kl);
    cudaGetSymbolAddress((void**)&v,    g_v);
    cudaGetSymbolAddress((void**)&vth,  g_vth);
    cudaGetSymbolAddress((void**)&vtl,  g_vtl);
    cudaGetSymbolAddress((void**)&atth, g_atth);
    cudaGetSymbolAddress((void**)&attl, g_attl);
    cudaGetSymbolAddress((void**)&y1,   g_y1);
    cudaGetSymbolAddress((void**)&xn2,  g_xn2);
    cudaGetSymbolAddress((void**)&xn2h, g_xn2h);
    cudaGetSymbolAddress((void**)&xn2l, g_xn2l);
    cudaGetSymbolAddress((void**)&hh,   g_hh);
    cudaGetSymbolAddress((void**)&hl,   g_hl);
    cudaGetSymbolAddress((void**)&wqkvh, g_wqkvh);
    cudaGetSymbolAddress((void**)&wqkvl, g_wqkvl);
    cudaGetSymbolAddress((void**)&wph,  g_wph);
    cudaGetSymbolAddress((void**)&wpl,  g_wpl);
    cudaGetSymbolAddress((void**)&w1h,  g_w1h);
    cudaGetSymbolAddress((void**)&w1l,  g_w1l);
    cudaGetSymbolAddress((void**)&w2h,  g_w2h);
    cudaGetSymbolAddress((void**)&w2l,  g_w2l);

    cudaFuncSetAttribute(mma_gemm, cudaFuncAttributeMaxDynamicSharedMemorySize, SMTOT);
    cudaFuncSetAttribute(attn_mma, cudaFuncAttributeMaxDynamicSharedMemorySize, ATT_SMEM);

    dim3 tb32(32, 8);
    qkv_prep_kernel<<<dim3(2, 32, 48), tb32>>>(wq, wk, wv, wqkvh, wqkvl);
    tconv_kernel<<<dim3(32, 32), tb32>>>(w_proj, wph, wpl, NE, NE, NE, 0);
    tconv_kernel<<<dim3(128, 32), tb32>>>(w1, w1h, w1l, NE, FF, NE, 0);
    tconv_kernel<<<dim3(32, 128), tb32>>>(w2, w2h, w2l, FF, NE, FF, 0);

    // 1) layernorm1
    ln_kernel<<<BT, 256>>>(x, g1, be1, xn1, xn1h, xn1l);

    // 2) fused QKV -> qh/ql, kh/kl (bf16), v (fp32)
    mma_gemm<<<dim3(24, 64), 256, SMTOT>>>(xn1h, xn1l, wqkvh, wqkvl, NE, 3 * NE,
                                           nullptr, nullptr, nullptr,
                                           qh, ql, kh, kl, v, 1);
    // 2b) V transpose + split
    vt_prep<<<dim3(TT / 32, HS / 32, NH * BD), tb32>>>(v, vth, vtl);

    // 3) tensor-core attention
    attn_mma<<<dim3(TT / 64, NH, BD), 128, ATT_SMEM>>>(qh, ql, kh, kl, vth, vtl,
                                                       atth, attl);

    // 4) proj + bias + residual(xn1) -> y1
    mma_gemm<<<dim3(8, 64), 256, SMTOT>>>(atth, attl, wph, wpl, NE, NE,
                                          b_proj, xn1, y1, nullptr, nullptr,
                                          nullptr, nullptr, nullptr, 0);
    // 5) layernorm2
    ln_kernel<<<BT, 256>>>(y1, g2, be2, xn2, xn2h, xn2l);

    // 6) FFN1 + bias + relu -> h (bf16 hi/lo)
    mma_gemm<<<dim3(32, 64), 256, SMTOT>>>(xn2h, xn2l, w1h, w1l, NE, FF,
                                           b1, nullptr, nullptr, hh, hl,
                                           nullptr, nullptr, nullptr, 2);
    // 7) FFN2 + bias + residual(xn2) -> out
    mma_gemm<<<dim3(8, 64), 256, SMTOT>>>(hh, hl, w2h, w2l, FF, NE,
                                          b2, xn2, out, nullptr, nullptr,
                                          nullptr, nullptr, nullptr, 0);
}

// round 14
// speedup vs baseline: 2.5648x; 1.0096x over previous
#include <cuda_runtime.h>
#include <cuda_bf16.h>
#include <stdint.h>
#include <math.h>

#define BD 8
#define TT 1024
#define NE 1024
#define NH 16
#define HS 64
#define BT (BD * TT)     // 8192
#define FF (4 * NE)      // 4096

// ---------------- scratch (alloc-guard-safe device globals) ----------------
__device__ float g_xn1[BT * NE];
__device__ __nv_bfloat16 g_xn1h[BT * NE], g_xn1l[BT * NE];
__device__ __nv_bfloat16 g_qh[NH * BT * HS], g_ql[NH * BT * HS];
__device__ __nv_bfloat16 g_kh[NH * BT * HS], g_kl[NH * BT * HS];
__device__ __nv_bfloat16 g_vth[NH * BT * HS], g_vtl[NH * BT * HS];  // [h][b][e][t]
__device__ __nv_bfloat16 g_atth[BT * NE], g_attl[BT * NE];
__device__ float g_y1[BT * NE];
__device__ float g_xn2[BT * NE];
__device__ __nv_bfloat16 g_xn2h[BT * NE], g_xn2l[BT * NE];
__device__ __nv_bfloat16 g_hh[(long)BT * FF], g_hl[(long)BT * FF];
__device__ __nv_bfloat16 g_wqkvh[3 * NE * NE], g_wqkvl[3 * NE * NE];
__device__ __nv_bfloat16 g_wph[NE * NE],  g_wpl[NE * NE];
__device__ __nv_bfloat16 g_w1h[FF * NE],  g_w1l[FF * NE];
__device__ __nv_bfloat16 g_w2h[NE * FF],  g_w2l[NE * FF];

// ---------------- helpers ----------------
__device__ __forceinline__ uint32_t smem_u32(const void* p) {
    uint32_t a;
    asm("{ .reg .u64 t; cvta.to.shared.u64 t, %1; cvt.u32.u64 %0, t; }"
        : "=r"(a) : "l"(p));
    return a;
}
__device__ __forceinline__ void splitf(float v, __nv_bfloat16& h, __nv_bfloat16& l) {
    h = __float2bfloat16(v);
    l = __float2bfloat16(v - __bfloat162float(h));
}
__device__ __forceinline__ void cp16(uint32_t dst, const void* src) {
    asm volatile("cp.async.cg.shared.global [%0], [%1], 16;"
                 :: "r"(dst), "l"(src) : "memory");
}
__device__ __forceinline__ void cp_commit() {
    asm volatile("cp.async.commit_group;" ::: "memory");
}
template <int N>
__device__ __forceinline__ void cp_wait() {
    asm volatile("cp.async.wait_group %0;" :: "n"(N) : "memory");
}
__device__ __forceinline__ void mma16816(float* c, const uint32_t* a,
                                         const uint32_t* b) {
    asm volatile(
        "mma.sync.aligned.m16n8k16.row.col.f32.bf16.bf16.f32 "
        "{%0,%1,%2,%3}, {%4,%5,%6,%7}, {%8,%9}, {%0,%1,%2,%3};"
        : "+f"(c[0]), "+f"(c[1]), "+f"(c[2]), "+f"(c[3])
        : "r"(a[0]), "r"(a[1]), "r"(a[2]), "r"(a[3]), "r"(b[0]), "r"(b[1]));
}
__device__ __forceinline__ void ldsm4(uint32_t* r, uint32_t addr) {
    asm volatile("ldmatrix.sync.aligned.m8n8.x4.shared.b16 {%0,%1,%2,%3}, [%4];"
                 : "=r"(r[0]), "=r"(r[1]), "=r"(r[2]), "=r"(r[3]) : "r"(addr));
}

// ---------------- layernorm: fp32 out + bf16 hi/lo out ----------------
__global__ __launch_bounds__(256) void ln_kernel(const float* __restrict__ x,
                                                 const float* __restrict__ g,
                                                 const float* __restrict__ be,
                                                 float* __restrict__ y,
                                                 __nv_bfloat16* __restrict__ yh,
                                                 __nv_bfloat16* __restrict__ yl) {
    __shared__ float sred[16];
    long row = blockIdx.x;
    const float4* xr = (const float4*)(x + row * NE);
    int tid = threadIdx.x;
    float4 t = xr[tid];
    float s  = t.x + t.y + t.z + t.w;
    float s2 = t.x * t.x + t.y * t.y + t.z * t.z + t.w * t.w;
    #pragma unroll
    for (int o = 16; o; o >>= 1) {
        s  += __shfl_xor_sync(0xffffffffu, s,  o);
        s2 += __shfl_xor_sync(0xffffffffu, s2, o);
    }
    int w = tid >> 5;
    if ((tid & 31) == 0) { sred[w] = s; sred[8 + w] = s2; }
    __syncthreads();
    if (tid < 32) {
        float a  = (tid < 8) ? sred[tid]     : 0.f;
        float a2 = (tid < 8) ? sred[8 + tid] : 0.f;
        #pragma unroll
        for (int o = 4; o; o >>= 1) {
            a  += __shfl_xor_sync(0xffffffffu, a,  o);
            a2 += __shfl_xor_sync(0xffffffffu, a2, o);
        }
        if (tid == 0) { sred[0] = a; sred[1] = a2; }
    }
    __syncthreads();
    float mean = sred[0] * (1.f / NE);
    float var  = sred[1] * (1.f / NE) - mean * mean;
    float rstd = rsqrtf(var + 1e-5f);
    float4 gg = ((const float4*)g)[tid];
    float4 bb = ((const float4*)be)[tid];
    float4 o;
    o.x = (t.x - mean) * rstd * gg.x + bb.x;
    o.y = (t.y - mean) * rstd * gg.y + bb.y;
    o.z = (t.z - mean) * rstd * gg.z + bb.z;
    o.w = (t.w - mean) * rstd * gg.w + bb.w;
    ((float4*)(y + row * NE))[tid] = o;
    __nv_bfloat16 h0, l0, h1, l1, h2, l2, h3, l3;
    splitf(o.x, h0, l0); splitf(o.y, h1, l1);
    splitf(o.z, h2, l2); splitf(o.w, h3, l3);
    __nv_bfloat162 H0; H0.x = h0; H0.y = h1;
    __nv_bfloat162 H1; H1.x = h2; H1.y = h3;
    __nv_bfloat162 L0; L0.x = l0; L0.y = l1;
    __nv_bfloat162 L1; L1.x = l2; L1.y = l3;
    __nv_bfloat162* ph = (__nv_bfloat162*)(yh + row * NE);
    __nv_bfloat162* pl = (__nv_bfloat162*)(yl + row * NE);
    ph[tid * 2] = H0; ph[tid * 2 + 1] = H1;
    pl[tid * 2] = L0; pl[tid * 2 + 1] = L1;
}

// ---------------- weight prep: transpose + bf16 split ----------------
__global__ __launch_bounds__(256) void tconv_kernel(const float* __restrict__ src,
                                                    __nv_bfloat16* __restrict__ dh,
                                                    __nv_bfloat16* __restrict__ dl,
                                                    int R, int C, int RS, int RO) {
    __shared__ float tile[32][33];
    int tx = threadIdx.x, ty = threadIdx.y;
    int x0 = blockIdx.x * 32, y0 = blockIdx.y * 32;
    #pragma unroll
    for (int i = 0; i < 4; i++)
        tile[ty + 8 * i][tx] = src[(long)(y0 + ty + 8 * i) * C + x0 + tx];
    __syncthreads();
    #pragma unroll
    for (int i = 0; i < 4; i++) {
        int c = x0 + ty + 8 * i;
        float v = tile[tx][ty + 8 * i];
        __nv_bfloat16 h, l; splitf(v, h, l);
        long di = (long)(RO + c) * RS + y0 + tx;
        dh[di] = h; dl[di] = l;
    }
}
__global__ __launch_bounds__(256) void qkv_prep_kernel(const float* __restrict__ wq,
                                                       const float* __restrict__ wk,
                                                       const float* __restrict__ wv,
                                                       __nv_bfloat16* __restrict__ dh,
                                                       __nv_bfloat16* __restrict__ dl) {
    __shared__ float tile[32][33];
    int z = blockIdx.z, which = z >> 4, h = z & 15;
    const float* src = ((which == 0) ? wq : (which == 1) ? wk : wv) + (long)h * NE * HS;
    int RO = which * NE + h * HS;
    int tx = threadIdx.x, ty = threadIdx.y;
    int x0 = blockIdx.x * 32, y0 = blockIdx.y * 32;
    #pragma unroll
    for (int i = 0; i < 4; i++)
        tile[ty + 8 * i][tx] = src[(long)(y0 + ty + 8 * i) * HS + x0 + tx];
    __syncthreads();
    #pragma unroll
    for (int i = 0; i < 4; i++) {
        int c = x0 + ty + 8 * i;
        float v = tile[tx][ty + 8 * i];
        __nv_bfloat16 hh, ll; splitf(v, hh, ll);
        long di = (long)(RO + c) * NE + y0 + tx;
        dh[di] = hh; dl[di] = ll;
    }
}

// ---------------- warp-MMA split-bf16 GEMM (R11 best config) ----------------
#define KC 32
#define ROWB 80
#define MATB (128 * ROWB)
#define STAGEB (4 * MATB)
#define SMTOT (2 * STAGEB)

__global__ __launch_bounds__(256, 2) void mma_gemm(
    const __nv_bfloat16* __restrict__ Ah, const __nv_bfloat16* __restrict__ Al,
    const __nv_bfloat16* __restrict__ Bh, const __nv_bfloat16* __restrict__ Bl,
    int Kdim, int Ndim,
    const float* __restrict__ bias, const float* __restrict__ res,
    float* __restrict__ Cf,
    __nv_bfloat16* __restrict__ Ch, __nv_bfloat16* __restrict__ Cl,
    __nv_bfloat16* __restrict__ Kh2, __nv_bfloat16* __restrict__ Kl2,
    __nv_bfloat16* __restrict__ Vth, __nv_bfloat16* __restrict__ Vtl,
    int mode) {
    extern __shared__ char smem[];
    uint32_t sb = smem_u32(smem);
    int tid = threadIdx.x;
    int wid = tid >> 5, lane = tid & 31;
    int warp_m = wid & 3, warp_n = wid >> 2;
    int r4 = lane >> 2, qp = lane & 3;
    int m0 = blockIdx.y * 128, n0 = blockIdx.x * 128;

    uint32_t a_off = (uint32_t)(warp_m * 32 + (lane & 15)) * ROWB + ((lane >> 4) << 4);
    uint32_t b_off = (uint32_t)(warp_n * 64 + ((lane >> 4) << 3) + (lane & 7)) * ROWB
                     + (((lane >> 3) & 1) << 4);

    float acc[2][8][4];
    #pragma unroll
    for (int mt = 0; mt < 2; mt++)
        #pragma unroll
        for (int nt = 0; nt < 8; nt++)
            #pragma unroll
            for (int e = 0; e < 4; e++) acc[mt][nt][e] = 0.f;

    int nch = Kdim / KC;

    auto issue = [&](int c, int st) {
        int k0 = c * KC;
        uint32_t sbase = sb + st * STAGEB;
        #pragma unroll
        for (int j = 0; j < 8; j++) {
            int i = tid + j * 256;
            int mat = i >> 9;
            int rem = i & 511;
            int r = rem >> 2, cc = rem & 3;
            const __nv_bfloat16* base =
                (mat == 0) ? Ah : (mat == 1) ? Al : (mat == 2) ? Bh : Bl;
            long grow = (mat < 2) ? ((long)(m0 + r) * Kdim)
                                  : ((long)(n0 + r) * Kdim);
            cp16(sbase + mat * MATB + r * ROWB + cc * 16,
                 base + grow + k0 + cc * 8);
        }
        cp_commit();
    };

    issue(0, 0);
    for (int c = 0; c < nch; c++) {
        int st = c & 1;
        if (c + 1 < nch) { issue(c + 1, st ^ 1); cp_wait<1>(); }
        else             { cp_wait<0>(); }
        __syncthreads();

        uint32_t stage = sb + st * STAGEB;
        #pragma unroll
        for (int ks = 0; ks < 2; ks++) {
            uint32_t ko = ks * 32;
            uint32_t ah[2][4], al[2][4], bh[4][4], bl[4][4];
            #pragma unroll
            for (int mt = 0; mt < 2; mt++) {
                uint32_t ra = stage + a_off + mt * (16 * ROWB) + ko;
                ldsm4(ah[mt], ra);
                ldsm4(al[mt], ra + MATB);
            }
            #pragma unroll
            for (int np = 0; np < 4; np++) {
                uint32_t rb = stage + 2 * MATB + b_off + np * (16 * ROWB) + ko;
                ldsm4(bh[np], rb);
                ldsm4(bl[np], rb + MATB);
            }
            #pragma unroll
            for (int mt = 0; mt < 2; mt++)
                #pragma unroll
                for (int np = 0; np < 4; np++) {
                    mma16816(acc[mt][np * 2],     ah[mt], &bh[np][0]);
                    mma16816(acc[mt][np * 2],     ah[mt], &bl[np][0]);
                    mma16816(acc[mt][np * 2],     al[mt], &bh[np][0]);
                    mma16816(acc[mt][np * 2 + 1], ah[mt], &bh[np][2]);
                    mma16816(acc[mt][np * 2 + 1], ah[mt], &bl[np][2]);
                    mma16816(acc[mt][np * 2 + 1], al[mt], &bh[np][2]);
                }
        }
        __syncthreads();
    }

    #pragma unroll
    for (int mt = 0; mt < 2; mt++) {
        int gm0 = m0 + warp_m * 32 + mt * 16 + r4;
        #pragma unroll
        for (int nt = 0; nt < 8; nt++) {
            int gn = n0 + warp_n * 64 + nt * 8 + 2 * qp;
            #pragma unroll
            for (int half = 0; half < 2; half++) {
                long gm = gm0 + half * 8;
                float v0 = acc[mt][nt][half * 2];
                float v1 = acc[mt][nt][half * 2 + 1];
                if (mode == 1) {
                    int which = gn >> 10, hd = (gn >> 6) & 15, e = gn & 63;
                    if (which == 2) {
                        // V: store transposed split-bf16 [hd][b][e][t]
                        int b = (int)(gm >> 10), t = (int)(gm & 1023);
                        long vbase = (long)(hd * BD + b) * HS * TT + t;
                        __nv_bfloat16 h0, l0, h1, l1;
                        splitf(v0, h0, l0); splitf(v1, h1, l1);
                        Vth[vbase + (long)e * TT]       = h0;
                        Vtl[vbase + (long)e * TT]       = l0;
                        Vth[vbase + (long)(e + 1) * TT] = h1;
                        Vtl[vbase + (long)(e + 1) * TT] = l1;
                    } else {
                        long idx = ((long)hd * BT + gm) * HS + e;
                        __nv_bfloat16 h0, l0, h1, l1;
                        splitf(v0, h0, l0); splitf(v1, h1, l1);
                        __nv_bfloat162 H; H.x = h0; H.y = h1;
                        __nv_bfloat162 L; L.x = l0; L.y = l1;
                        __nv_bfloat16* dh = (which == 0) ? Ch : Kh2;
                        __nv_bfloat16* dl = (which == 0) ? Cl : Kl2;
                        *(__nv_bfloat162*)(dh + idx) = H;
                        *(__nv_bfloat162*)(dl + idx) = L;
                    }
                } else if (mode == 2) {
                    v0 = fmaxf(v0 + bias[gn], 0.f);
                    v1 = fmaxf(v1 + bias[gn + 1], 0.f);
                    __nv_bfloat16 h0, l0, h1, l1;
                    splitf(v0, h0, l0); splitf(v1, h1, l1);
                    __nv_bfloat162 H; H.x = h0; H.y = h1;
                    __nv_bfloat162 L; L.x = l0; L.y = l1;
                    long idx = (gm * (long)Ndim + gn) >> 1;
                    ((__nv_bfloat162*)Ch)[idx] = H;
                    ((__nv_bfloat162*)Cl)[idx] = L;
                } else {
                    if (bias) { v0 += bias[gn]; v1 += bias[gn + 1]; }
                    if (res) {
                        float2 rr = *(const float2*)(res + gm * (long)Ndim + gn);
                        v0 += rr.x; v1 += rr.y;
                    }
                    float2 t; t.x = v0; t.y = v1;
                    *(float2*)(Cf + gm * (long)Ndim + gn) = t;
                }
            }
        }
    }
}

// ---------------- tensor-core causal attention (split-bf16, flash-style) ----
#define AROW 144
#define ATILE (64 * AROW)
#define SQ_H 0
#define SQ_L ATILE
#define SK_H (2 * ATILE)
#define SK_L (3 * ATILE)
#define SV_H (4 * ATILE)
#define SV_L (5 * ATILE)
#define ATT_SMEM (6 * ATILE)           // 55296 B

__global__ __launch_bounds__(128) void attn_mma(
    const __nv_bfloat16* __restrict__ Qh, const __nv_bfloat16* __restrict__ Ql,
    const __nv_bfloat16* __restrict__ Kh, const __nv_bfloat16* __restrict__ Kl,
    const __nv_bfloat16* __restrict__ Vth, const __nv_bfloat16* __restrict__ Vtl,
    __nv_bfloat16* __restrict__ Oh, __nv_bfloat16* __restrict__ Ol) {
    extern __shared__ char smem[];
    uint32_t sb = smem_u32(smem);
    int tid = threadIdx.x, wid = tid >> 5, lane = tid & 31;
    int r4 = lane >> 2, qp = lane & 3;
    int q0 = blockIdx.x * 64, h = blockIdx.y, b = blockIdx.z;
    long qk_base = ((long)h * BT + (long)b * TT) * HS;
    long vt_base = (long)(h * BD + b) * HS * TT;

    for (int i = tid; i < 64 * 8; i += 128) {
        int r = i >> 3, c = i & 7;
        long g = qk_base + (long)(q0 + r) * HS + c * 8;
        *(uint4*)(smem + SQ_H + r * AROW + c * 16) = *(const uint4*)(Qh + g);
        *(uint4*)(smem + SQ_L + r * AROW + c * 16) = *(const uint4*)(Ql + g);
    }
    __syncthreads();
    uint32_t a_off = (uint32_t)(wid * 16 + (lane & 15)) * AROW + ((lane >> 4) << 4);
    uint32_t qfh[4][4], qfl[4][4];
    #pragma unroll
    for (int kc = 0; kc < 4; kc++) {
        ldsm4(qfh[kc], sb + SQ_H + a_off + kc * 32);
        ldsm4(qfl[kc], sb + SQ_L + a_off + kc * 32);
    }

    uint32_t b_off = (uint32_t)(((lane >> 4) << 3) + (lane & 7)) * AROW
                     + (((lane >> 3) & 1) << 4);

    float o_acc[8][4];
    #pragma unroll
    for (int nt = 0; nt < 8; nt++)
        #pragma unroll
        for (int e = 0; e < 4; e++) o_acc[nt][e] = 0.f;
    float lsum0 = 0.f, lsum1 = 0.f;
    const float scale = 0.125f;
    int qrow0 = q0 + wid * 16 + r4;

    int ntiles = q0 / 64 + 1;
    for (int ti = 0; ti < ntiles; ti++) {
        int s0 = ti * 64;
        __syncthreads();
        for (int i = tid; i < 64 * 8; i += 128) {
            int r = i >> 3, c = i & 7;
            long gk = qk_base + (long)(s0 + r) * HS + c * 8;
            long gv = vt_base + (long)r * TT + s0 + c * 8;
            *(uint4*)(smem + SK_H + r * AROW + c * 16) = *(const uint4*)(Kh + gk);
            *(uint4*)(smem + SK_L + r * AROW + c * 16) = *(const uint4*)(Kl + gk);
            *(uint4*)(smem + SV_H + r * AROW + c * 16) = *(const uint4*)(Vth + gv);
            *(uint4*)(smem + SV_L + r * AROW + c * 16) = *(const uint4*)(Vtl + gv);
        }
        __syncthreads();

        float s_acc[8][4];
        #pragma unroll
        for (int nt = 0; nt < 8; nt++)
            #pragma unroll
            for (int e = 0; e < 4; e++) s_acc[nt][e] = 0.f;
        #pragma unroll
        for (int kc = 0; kc < 4; kc++) {
            uint32_t kbh[4][4], kbl[4][4];
            #pragma unroll
            for (int np = 0; np < 4; np++) {
                uint32_t rb = sb + b_off + np * (16 * AROW) + kc * 32;
                ldsm4(kbh[np], rb + SK_H);
                ldsm4(kbl[np], rb + SK_L);
            }
            #pragma unroll
            for (int np = 0; np < 4; np++) {
                mma16816(s_acc[np * 2],     qfh[kc], &kbh[np][0]);
                mma16816(s_acc[np * 2],     qfh[kc], &kbl[np][0]);
                mma16816(s_acc[np * 2],     qfl[kc], &kbh[np][0]);
                mma16816(s_acc[np * 2 + 1], qfh[kc], &kbh[np][2]);
                mma16816(s_acc[np * 2 + 1], qfh[kc], &kbl[np][2]);
                mma16816(s_acc[np * 2 + 1], qfl[kc], &kbh[np][2]);
            }
        }

        bool diag = (s0 == q0);
        uint32_t pah[4][4], pal[4][4];
        #pragma unroll
        for (int nt = 0; nt < 8; nt++) {
            int scol = s0 + nt * 8 + 2 * qp;
            float e0 = (!diag || scol     <= qrow0)     ? __expf(s_acc[nt][0] * scale) : 0.f;
            float e1 = (!diag || scol + 1 <= qrow0)     ? __expf(s_acc[nt][1] * scale) : 0.f;
            float e2 = (!diag || scol     <= qrow0 + 8) ? __expf(s_acc[nt][2] * scale) : 0.f;
            float e3 = (!diag || scol + 1 <= qrow0 + 8) ? __expf(s_acc[nt][3] * scale) : 0.f;
            lsum0 += e0 + e1; lsum1 += e2 + e3;
            __nv_bfloat16 h0, l0, h1, l1, h2, l2, h3, l3;
            splitf(e0, h0, l0); splitf(e1, h1, l1);
            splitf(e2, h2, l2); splitf(e3, h3, l3);
            __nv_bfloat162 H01; H01.x = h0; H01.y = h1;
            __nv_bfloat162 H23; H23.x = h2; H23.y = h3;
            __nv_bfloat162 L01; L01.x = l0; L01.y = l1;
            __nv_bfloat162 L23; L23.x = l2; L23.y = l3;
            int j = nt >> 1, hf = (nt & 1) * 2;
            pah[j][hf]     = *(uint32_t*)&H01;
            pah[j][hf + 1] = *(uint32_t*)&H23;
            pal[j][hf]     = *(uint32_t*)&L01;
            pal[j][hf + 1] = *(uint32_t*)&L23;
        }

        #pragma unroll
        for (int kc = 0; kc < 4; kc++) {
            uint32_t vbh[4][4], vbl[4][4];
            #pragma unroll
            for (int np = 0; np < 4; np++) {
                uint32_t rb = sb + b_off + np * (16 * AROW) + kc * 32;
                ldsm4(vbh[np], rb + SV_H);
                ldsm4(vbl[np], rb + SV_L);
            }
            #pragma unroll
            for (int np = 0; np < 4; np++) {
                mma16816(o_acc[np * 2],     pah[kc], &vbh[np][0]);
                mma16816(o_acc[np * 2],     pah[kc], &vbl[np][0]);
                mma16816(o_acc[np * 2],     pal[kc], &vbh[np][0]);
                mma16816(o_acc[np * 2 + 1], pah[kc], &vbh[np][2]);
                mma16816(o_acc[np * 2 + 1], pah[kc], &vbl[np][2]);
                mma16816(o_acc[np * 2 + 1], pal[kc], &vbh[np][2]);
            }
        }
    }

    lsum0 += __shfl_xor_sync(0xffffffffu, lsum0, 1);
    lsum0 += __shfl_xor_sync(0xffffffffu, lsum0, 2);
    lsum1 += __shfl_xor_sync(0xffffffffu, lsum1, 1);
    lsum1 += __shfl_xor_sync(0xffffffffu, lsum1, 2);
    float inv0 = 1.f / lsum0, inv1 = 1.f / lsum1;

    #pragma unroll
    for (int nt = 0; nt < 8; nt++) {
        int e = nt * 8 + 2 * qp;
        long i0 = ((long)(b * TT) + qrow0) * NE + h * HS + e;
        long i1 = i0 + 8L * NE;
        float v0 = o_acc[nt][0] * inv0, v1 = o_acc[nt][1] * inv0;
        float v2 = o_acc[nt][2] * inv1, v3 = o_acc[nt][3] * inv1;
        __nv_bfloat16 h0, l0, h1, l1; splitf(v0, h0, l0); splitf(v1, h1, l1);
        __nv_bfloat162 H; H.x = h0; H.y = h1;
        __nv_bfloat162 L; L.x = l0; L.y = l1;
        *(__nv_bfloat162*)(Oh + i0) = H;
        *(__nv_bfloat162*)(Ol + i0) = L;
        __nv_bfloat16 h2, l2, h3, l3; splitf(v2, h2, l2); splitf(v3, h3, l3);
        __nv_bfloat162 H2; H2.x = h2; H2.y = h3;
        __nv_bfloat162 L2; L2.x = l2; L2.y = l3;
        *(__nv_bfloat162*)(Oh + i1) = H2;
        *(__nv_bfloat162*)(Ol + i1) = L2;
    }
}

// ---------------- launch ----------------
extern "C" void kernel_launch(void* const* d_in, const int* in_sizes, int n_in,
                              void* d_out, int out_size) {
    const float* x      = (const float*)d_in[0];
    const float* wq     = (const float*)d_in[1];
    const float* wk     = (const float*)d_in[2];
    const float* wv     = (const float*)d_in[3];
    const float* w_proj = (const float*)d_in[4];
    const float* b_proj = (const float*)d_in[5];
    const float* w1     = (const float*)d_in[6];
    const float* b1     = (const float*)d_in[7];
    const float* w2     = (const float*)d_in[8];
    const float* b2     = (const float*)d_in[9];
    const float* g1     = (const float*)d_in[10];
    const float* be1    = (const float*)d_in[11];
    const float* g2     = (const float*)d_in[12];
    const float* be2    = (const float*)d_in[13];
    float* out = (float*)d_out;

    float *xn1, *y1, *xn2;
    __nv_bfloat16 *xn1h, *xn1l, *qh, *ql, *kh, *kl, *vth, *vtl;
    __nv_bfloat16 *atth, *attl, *xn2h, *xn2l, *hh, *hl;
    __nv_bfloat16 *wqkvh, *wqkvl, *wph, *wpl, *w1h, *w1l, *w2h, *w2l;
    cudaGetSymbolAddress((void**)&xn1,  g_xn1);
    cudaGetSymbolAddress((void**)&xn1h, g_xn1h);
    cudaGetSymbolAddress((void**)&xn1l, g_xn1l);
    cudaGetSymbolAddress((void**)&qh,   g_qh);
    cudaGetSymbolAddress((void**)&ql,   g_ql);
    cudaGetSymbolAddress((void**)&kh,   g_kh);
    cudaGetSymbolAddress((void**)&kl,   g_kl);
    cudaGetSymbolAddress((void**)&vth,  g_vth);
    cudaGetSymbolAddress((void**)&vtl,  g_vtl);
    cudaGetSymbolAddress((void**)&atth, g_atth);
    cudaGetSymbolAddress((void**)&attl, g_attl);
    cudaGetSymbolAddress((void**)&y1,   g_y1);
    cudaGetSymbolAddress((void**)&xn2,  g_xn2);
    cudaGetSymbolAddress((void**)&xn2h, g_xn2h);
    cudaGetSymbolAddress((void**)&xn2l, g_xn2l);
    cudaGetSymbolAddress((void**)&hh,   g_hh);
    cudaGetSymbolAddress((void**)&hl,   g_hl);
    cudaGetSymbolAddress((void**)&wqkvh, g_wqkvh);
    cudaGetSymbolAddress((void**)&wqkvl, g_wqkvl);
    cudaGetSymbolAddress((void**)&wph,  g_wph);
    cudaGetSymbolAddress((void**)&wpl,  g_wpl);
    cudaGetSymbolAddress((void**)&w1h,  g_w1h);
    cudaGetSymbolAddress((void**)&w1l,  g_w1l);
    cudaGetSymbolAddress((void**)&w2h,  g_w2h);
    cudaGetSymbolAddress((void**)&w2l,  g_w2l);

    cudaFuncSetAttribute(mma_gemm, cudaFuncAttributeMaxDynamicSharedMemorySize, SMTOT);
    cudaFuncSetAttribute(attn_mma, cudaFuncAttributeMaxDynamicSharedMemorySize, ATT_SMEM);

    dim3 tb32(32, 8);
    // 1) qkv weight prep
    qkv_prep_kernel<<<dim3(2, 32, 48), tb32>>>(wq, wk, wv, wqkvh, wqkvl);
    // 2) layernorm1
    ln_kernel<<<BT, 256>>>(x, g1, be1, xn1, xn1h, xn1l);
    // 3) fused QKV -> qh/ql, kh/kl (bf16), V transposed split (vth/vtl)
    mma_gemm<<<dim3(24, 64), 256, SMTOT>>>(xn1h, xn1l, wqkvh, wqkvl, NE, 3 * NE,
                                           nullptr, nullptr, nullptr,
                                           qh, ql, kh, kl, vth, vtl, 1);
    // 4) w_proj prep
    tconv_kernel<<<dim3(32, 32), tb32>>>(w_proj, wph, wpl, NE, NE, NE, 0);
    // 5) tensor-core attention
    attn_mma<<<dim3(TT / 64, NH, BD), 128, ATT_SMEM>>>(qh, ql, kh, kl, vth, vtl,
                                                       atth, attl);
    // 6) proj + bias + residual(xn1) -> y1
    mma_gemm<<<dim3(8, 64), 256, SMTOT>>>(atth, attl, wph, wpl, NE, NE,
                                          b_proj, xn1, y1, nullptr, nullptr,
                                          nullptr, nullptr, nullptr, nullptr, 0);
    // 7) layernorm2
    ln_kernel<<<BT, 256>>>(y1, g2, be2, xn2, xn2h, xn2l);
    // 8) w1 prep
    tconv_kernel<<<dim3(128, 32), tb32>>>(w1, w1h, w1l, NE, FF, NE, 0);
    // 9) FFN1 + bias + relu -> h (bf16 hi/lo)
    mma_gemm<<<dim3(32, 64), 256, SMTOT>>>(xn2h, xn2l, w1h, w1l, NE, FF,
                                           b1, nullptr, nullptr, hh, hl,
                                           nullptr, nullptr, nullptr, nullptr, 2);
    // 10) w2 prep
    tconv_kernel<<<dim3(32, 128), tb32>>>(w2, w2h, w2l, FF, NE, FF, 0);
    // 11) FFN2 + bias + residual(xn2) -> out
    mma_gemm<<<dim3(8, 64), 256, SMTOT>>>(hh, hl, w2h, w2l, FF, NE,
                                          b2, xn2, out, nullptr, nullptr,
                                          nullptr, nullptr, nullptr, nullptr, 0);
}